// round 1
// baseline (speedup 1.0000x reference)
#include <cuda_runtime.h>
#include <math.h>

#define CC 1024
#define C4 (CC/4)
#define HH 128
#define WW 128
#define HW (HH*WW)
#define NP 4096
#define SRINV 0.125f
#define NITERS 10

// ---------------- device state (static globals: no runtime allocation) ----------------
__device__ float d_img0T[HW*CC];   // imgf0 transposed to [H,W,C]
__device__ float d_img1T[HW*CC];   // imgf1 transposed to [H,W,C]
__device__ float d_gxT[HW*CC];     // sobel-x of imgf1, [H,W,C]
__device__ float d_gyT[HW*CC];     // sobel-y of imgf1, [H,W,C]
__device__ float d_feat0[NP*CC];   // reference features per point
__device__ float d_pts3d0[NP*3];
__device__ float d_part[27*NP];    // per-point g(6)+H-upper(21) partials
__device__ float d_costpt[NP];
__device__ float d_candp2[NP*2];
__device__ float d_R[9];
__device__ float d_t[3];
__device__ float d_Rc[9];
__device__ float d_tc[3];
__device__ float d_lam;
__device__ float d_prev;
__device__ float d_acc;
__device__ float d_Hm[36];
__device__ float d_gv[6];

// ---------------- prep: CHW -> HWC transpose ----------------
__global__ void k_transpose(const float* __restrict__ src, int dst_sel) {
    float* dst = dst_sel ? d_img1T : d_img0T;
    __shared__ float tile[32][33];
    int hw0 = blockIdx.x * 32;
    int c0  = blockIdx.y * 32;
#pragma unroll
    for (int i = threadIdx.y; i < 32; i += 8)
        tile[i][threadIdx.x] = src[(size_t)(c0 + i) * HW + hw0 + threadIdx.x];
    __syncthreads();
#pragma unroll
    for (int i = threadIdx.y; i < 32; i += 8)
        dst[(size_t)(hw0 + i) * CC + c0 + threadIdx.x] = tile[threadIdx.x][i];
}

// ---------------- prep: sobel (cross-correlation, zero pad) in HWC ----------------
__global__ void __launch_bounds__(256) k_sobel() {
    int x = blockIdx.x, y = blockIdx.y;
    int c = threadIdx.x;  // float4 channel group, 256 covers 1024 channels
    const float4* img = reinterpret_cast<const float4*>(d_img1T);
    float4 v[3][3];
#pragma unroll
    for (int dy = -1; dy <= 1; dy++) {
#pragma unroll
        for (int dx = -1; dx <= 1; dx++) {
            int yy = y + dy, xx = x + dx;
            float4 val = make_float4(0.f, 0.f, 0.f, 0.f);
            if (yy >= 0 && yy < HH && xx >= 0 && xx < WW)
                val = img[(size_t)(yy * WW + xx) * C4 + c];
            v[dy+1][dx+1] = val;
        }
    }
    float4 gx, gy;
#define SOB(cmp) \
    gx.cmp = (v[0][2].cmp - v[0][0].cmp + 2.f*(v[1][2].cmp - v[1][0].cmp) + v[2][2].cmp - v[2][0].cmp) * 0.125f; \
    gy.cmp = (v[2][0].cmp - v[0][0].cmp + 2.f*(v[2][1].cmp - v[0][1].cmp) + v[2][2].cmp - v[0][2].cmp) * 0.125f;
    SOB(x) SOB(y) SOB(z) SOB(w)
#undef SOB
    size_t o = (size_t)(y * WW + x) * C4 + c;
    reinterpret_cast<float4*>(d_gxT)[o] = gx;
    reinterpret_cast<float4*>(d_gyT)[o] = gy;
}

// ---------------- bilinear setup helper ----------------
struct BilinSetup {
    int b00, b10, b01, b11;   // float4 base indices
    float w00, w10, w01, w11;
};
__device__ __forceinline__ BilinSetup bilin_setup(float x, float y) {
    BilinSetup s;
    float x0f = floorf(x), y0f = floorf(y);
    float wx = x - x0f, wy = y - y0f;
    int x0 = min(max((int)x0f, 0), WW-1);
    int x1 = min(max(x0 + 1, 0), WW-1);
    int y0 = min(max((int)y0f, 0), HH-1);
    int y1 = min(max(y0 + 1, 0), HH-1);
    s.w00 = (1.f-wx)*(1.f-wy); s.w10 = wx*(1.f-wy);
    s.w01 = (1.f-wx)*wy;       s.w11 = wx*wy;
    s.b00 = (y0*WW + x0) * C4; s.b10 = (y0*WW + x1) * C4;
    s.b01 = (y1*WW + x0) * C4; s.b11 = (y1*WW + x1) * C4;
    return s;
}
__device__ __forceinline__ float bil(float a, float b, float c, float d, const BilinSetup& s) {
    return a*s.w00 + b*s.w10 + c*s.w01 + d*s.w11;
}

// ---------------- prep: feat0 ----------------
__global__ void __launch_bounds__(256) k_feat0(const float* __restrict__ pts2d) {
    int n = blockIdx.x;
    BilinSetup s = bilin_setup(pts2d[2*n] * SRINV, pts2d[2*n+1] * SRINV);
    const float4* img = reinterpret_cast<const float4*>(d_img0T);
    int c = threadIdx.x;
    float4 f00 = img[(size_t)s.b00 + c], f10 = img[(size_t)s.b10 + c];
    float4 f01 = img[(size_t)s.b01 + c], f11 = img[(size_t)s.b11 + c];
    float4 o;
    o.x = bil(f00.x, f10.x, f01.x, f11.x, s);
    o.y = bil(f00.y, f10.y, f01.y, f11.y, s);
    o.z = bil(f00.z, f10.z, f01.z, f11.z, s);
    o.w = bil(f00.w, f10.w, f01.w, f11.w, s);
    reinterpret_cast<float4*>(d_feat0)[(size_t)n * C4 + c] = o;
}

// ---------------- prep: pts3d0 = from_homog(r @ [p;1]) ----------------
__global__ void k_pts3d0(const float* __restrict__ p3d, const float* __restrict__ rm) {
    int n = blockIdx.x * blockDim.x + threadIdx.x;
    if (n >= NP) return;
    float X = p3d[3*n], Y = p3d[3*n+1], Z = p3d[3*n+2];
    float px = rm[0]*X + rm[1]*Y + rm[2]*Z + rm[3];
    float py = rm[4]*X + rm[5]*Y + rm[6]*Z + rm[7];
    float pz = rm[8]*X + rm[9]*Y + rm[10]*Z + rm[11];
    float pw = rm[12]*X + rm[13]*Y + rm[14]*Z + rm[15];
    d_pts3d0[3*n]   = px / pw;
    d_pts3d0[3*n+1] = py / pw;
    d_pts3d0[3*n+2] = pz / pw;
}

// ---------------- init: relative = q @ inv(r) ----------------
__global__ void k_init_state(const float* __restrict__ q, const float* __restrict__ r) {
    double M[4][8];
    for (int i = 0; i < 4; i++)
        for (int j = 0; j < 4; j++) { M[i][j] = r[i*4+j]; M[i][4+j] = (i == j) ? 1.0 : 0.0; }
    for (int col = 0; col < 4; col++) {
        int piv = col; double best = fabs(M[col][col]);
        for (int i = col+1; i < 4; i++) if (fabs(M[i][col]) > best) { best = fabs(M[i][col]); piv = i; }
        if (piv != col) for (int j = 0; j < 8; j++) { double tmp = M[col][j]; M[col][j] = M[piv][j]; M[piv][j] = tmp; }
        double inv = 1.0 / M[col][col];
        for (int j = 0; j < 8; j++) M[col][j] *= inv;
        for (int i = 0; i < 4; i++) if (i != col) {
            double f = M[i][col];
            for (int j = 0; j < 8; j++) M[i][j] -= f * M[col][j];
        }
    }
    for (int i = 0; i < 3; i++) {
        for (int j = 0; j < 4; j++) {
            double s = 0.0;
            for (int k = 0; k < 4; k++) s += (double)q[i*4+k] * M[k][4+j];
            if (j < 3) { d_R[i*3+j] = (float)s; d_Rc[i*3+j] = (float)s; }
            else       { d_t[i] = (float)s; d_tc[i] = (float)s; }
        }
    }
    d_lam = 0.01f;
}

// ---------------- per-point projection helper ----------------
__device__ __forceinline__ void project_pt(int n, const float* R, const float* t,
                                           const float* __restrict__ Km,
                                           float& px, float& py, float& pz,
                                           float& p2x, float& p2y) {
    float X = d_pts3d0[3*n], Y = d_pts3d0[3*n+1], Z = d_pts3d0[3*n+2];
    px = R[0]*X + R[1]*Y + R[2]*Z + t[0];
    py = R[3]*X + R[4]*Y + R[5]*Z + t[1];
    pz = R[6]*X + R[7]*Y + R[8]*Z + t[2];
    float qx = Km[0]*px + Km[1]*py + Km[2]*pz;
    float qy = Km[3]*px + Km[4]*py + Km[5]*pz;
    float qz = Km[6]*px + Km[7]*py + Km[8]*pz;
    p2x = qx / qz; p2y = qy / qz;
}

// ---------------- main: Jacobian reductions per point ----------------
__global__ void __launch_bounds__(256) k_jac(const float* __restrict__ Km) {
    int n = blockIdx.x;
    int tid = threadIdx.x;
    float R[9], t[3];
#pragma unroll
    for (int i = 0; i < 9; i++) R[i] = d_R[i];
#pragma unroll
    for (int i = 0; i < 3; i++) t[i] = d_t[i];
    float px, py, pz, p2x, p2y;
    project_pt(n, R, t, Km, px, py, pz, p2x, p2y);
    float ix = fminf(fmaxf(p2x * SRINV, 0.f), (float)(WW-1));
    float iy = fminf(fmaxf(p2y * SRINV, 0.f), (float)(HH-1));
    BilinSetup s = bilin_setup(ix, iy);

    const float4* I1 = reinterpret_cast<const float4*>(d_img1T);
    const float4* GX = reinterpret_cast<const float4*>(d_gxT);
    const float4* GY = reinterpret_cast<const float4*>(d_gyT);
    const float4* F0 = reinterpret_cast<const float4*>(d_feat0) + (size_t)n * C4;

    int c = tid;
    float4 i00 = I1[(size_t)s.b00 + c], i10 = I1[(size_t)s.b10 + c];
    float4 i01 = I1[(size_t)s.b01 + c], i11 = I1[(size_t)s.b11 + c];
    float4 gx00 = GX[(size_t)s.b00 + c], gx10 = GX[(size_t)s.b10 + c];
    float4 gx01 = GX[(size_t)s.b01 + c], gx11 = GX[(size_t)s.b11 + c];
    float4 gy00 = GY[(size_t)s.b00 + c], gy10 = GY[(size_t)s.b10 + c];
    float4 gy01 = GY[(size_t)s.b01 + c], gy11 = GY[(size_t)s.b11 + c];
    float4 f0 = F0[c];

    float sx = 0.f, sy = 0.f, sxx = 0.f, sxy = 0.f, syy = 0.f;
#define PROC(cmp) { \
    float f1 = bil(i00.cmp, i10.cmp, i01.cmp, i11.cmp, s); \
    float jx = bil(gx00.cmp, gx10.cmp, gx01.cmp, gx11.cmp, s); \
    float jy = bil(gy00.cmp, gy10.cmp, gy01.cmp, gy11.cmp, s); \
    float e = f1 - f0.cmp; \
    sx += jx*e; sy += jy*e; sxx += jx*jx; sxy += jx*jy; syy += jy*jy; }
    PROC(x) PROC(y) PROC(z) PROC(w)
#undef PROC

    // block reduction (deterministic)
#pragma unroll
    for (int off = 16; off; off >>= 1) {
        sx  += __shfl_down_sync(0xffffffffu, sx,  off);
        sy  += __shfl_down_sync(0xffffffffu, sy,  off);
        sxx += __shfl_down_sync(0xffffffffu, sxx, off);
        sxy += __shfl_down_sync(0xffffffffu, sxy, off);
        syy += __shfl_down_sync(0xffffffffu, syy, off);
    }
    __shared__ float sm[8][5];
    int wid = tid >> 5, lane = tid & 31;
    if (lane == 0) { sm[wid][0] = sx; sm[wid][1] = sy; sm[wid][2] = sxx; sm[wid][3] = sxy; sm[wid][4] = syy; }
    __syncthreads();
    if (tid == 0) {
        float SX = 0.f, SY = 0.f, SXX = 0.f, SXY = 0.f, SYY = 0.f;
#pragma unroll
        for (int w = 0; w < 8; w++) { SX += sm[w][0]; SY += sm[w][1]; SXX += sm[w][2]; SXY += sm[w][3]; SYY += sm[w][4]; }

        float fx = Km[0], fy = Km[4];
        float invz = 1.f / pz;
        float sc = invz * SRINV;            // 1/(z * SIZE_RATIO)
        float a00 = fx * sc, a01 = 0.f, a02 = -fx * px * invz * sc;
        float a10 = 0.f, a11 = fy * sc, a12 = -fy * py * invz * sc;
        // A[:,3:] = -J_h_p @ skew(p3)
        float A0[6], A1[6];
        A0[0] = a00; A0[1] = a01; A0[2] = a02;
        A1[0] = a10; A1[1] = a11; A1[2] = a12;
        A0[3] = -(a01*pz - a02*py);
        A0[4] = -(-a00*pz + a02*px);
        A0[5] = -(a00*py - a01*px);
        A1[3] = -(a11*pz - a12*py);
        A1[4] = -(-a10*pz + a12*px);
        A1[5] = -(a10*py - a11*px);

        // per-point g and H(upper) contributions
#pragma unroll
        for (int k = 0; k < 6; k++)
            d_part[k*NP + n] = SX*A0[k] + SY*A1[k];
        int idx = 6;
#pragma unroll
        for (int k = 0; k < 6; k++)
#pragma unroll
            for (int l = k; l < 6; l++) {
                d_part[idx*NP + n] = SXX*A0[k]*A0[l] + SXY*(A0[k]*A1[l] + A1[k]*A0[l]) + SYY*A1[k]*A1[l];
                idx++;
            }
    }
}

// ---------------- deterministic reduce of g/H over points ----------------
__global__ void __launch_bounds__(256) k_reduce_jac() {
    int tid = threadIdx.x;
    float acc[27];
#pragma unroll
    for (int k = 0; k < 27; k++) acc[k] = 0.f;
    for (int n = tid; n < NP; n += 256)
#pragma unroll
        for (int k = 0; k < 27; k++) acc[k] += d_part[k*NP + n];
    __shared__ float sm[27][256];
#pragma unroll
    for (int k = 0; k < 27; k++) sm[k][tid] = acc[k];
    __syncthreads();
    for (int sgap = 128; sgap; sgap >>= 1) {
        if (tid < sgap)
#pragma unroll
            for (int k = 0; k < 27; k++) sm[k][tid] += sm[k][tid + sgap];
        __syncthreads();
    }
    if (tid == 0) {
#pragma unroll
        for (int k = 0; k < 6; k++) d_gv[k] = sm[k][0];
        int idx = 6;
        for (int k = 0; k < 6; k++)
            for (int l = k; l < 6; l++) {
                d_Hm[k*6+l] = sm[idx][0];
                d_Hm[l*6+k] = sm[idx][0];
                idx++;
            }
    }
}

// ---------------- LM solve + pose update (candidate) ----------------
__global__ void k_solve() {
    double Hd[6][7];
    double lam = (double)d_lam;
    for (int k = 0; k < 6; k++) {
        for (int l = 0; l < 6; l++) Hd[k][l] = (double)d_Hm[k*6+l];
        Hd[k][k] += ((double)d_Hm[k*6+k] + 1e-9) * lam;
        Hd[k][6] = -(double)d_gv[k];
    }
    for (int col = 0; col < 6; col++) {
        int piv = col; double best = fabs(Hd[col][col]);
        for (int r = col+1; r < 6; r++) if (fabs(Hd[r][col]) > best) { best = fabs(Hd[r][col]); piv = r; }
        if (piv != col) for (int j = 0; j < 7; j++) { double tmp = Hd[col][j]; Hd[col][j] = Hd[piv][j]; Hd[piv][j] = tmp; }
        double ip = 1.0 / Hd[col][col];
        for (int r = col+1; r < 6; r++) {
            double f = Hd[r][col] * ip;
            for (int j = col; j < 7; j++) Hd[r][j] -= f * Hd[col][j];
        }
    }
    double delta[6];
    for (int r = 5; r >= 0; r--) {
        double sv = Hd[r][6];
        for (int j = r+1; j < 6; j++) sv -= Hd[r][j] * delta[j];
        delta[r] = sv / Hd[r][r];
    }
    double w0 = delta[3], w1 = delta[4], w2 = delta[5];
    double th2 = w0*w0 + w1*w1 + w2*w2;
    double th = sqrt(fmax(th2, 1e-24));
    double Ac = (th2 < 1e-16) ? 1.0 : sin(th) / th;
    double Bc = (th2 < 1e-16) ? 0.5 : (1.0 - cos(th)) / fmax(th2, 1e-24);
    double dr[3][3];
    dr[0][0] = 1.0 + Bc*(w0*w0 - th2);
    dr[0][1] = -Ac*w2 + Bc*w0*w1;
    dr[0][2] =  Ac*w1 + Bc*w0*w2;
    dr[1][0] =  Ac*w2 + Bc*w1*w0;
    dr[1][1] = 1.0 + Bc*(w1*w1 - th2);
    dr[1][2] = -Ac*w0 + Bc*w1*w2;
    dr[2][0] = -Ac*w1 + Bc*w2*w0;
    dr[2][1] =  Ac*w0 + Bc*w2*w1;
    dr[2][2] = 1.0 + Bc*(w2*w2 - th2);
    for (int i = 0; i < 3; i++) {
        for (int j = 0; j < 3; j++) {
            double sv = 0.0;
            for (int k = 0; k < 3; k++) sv += dr[i][k] * (double)d_R[k*3+j];
            d_Rc[i*3+j] = (float)sv;
        }
        double sv = delta[i];
        for (int k = 0; k < 3; k++) sv += dr[i][k] * (double)d_t[k];
        d_tc[i] = (float)sv;
    }
}

// ---------------- candidate cost per point ----------------
__global__ void __launch_bounds__(256) k_cost(const float* __restrict__ Km) {
    int n = blockIdx.x;
    int tid = threadIdx.x;
    float R[9], t[3];
#pragma unroll
    for (int i = 0; i < 9; i++) R[i] = d_Rc[i];
#pragma unroll
    for (int i = 0; i < 3; i++) t[i] = d_tc[i];
    float px, py, pz, p2x, p2y;
    project_pt(n, R, t, Km, px, py, pz, p2x, p2y);
    float ix = fminf(fmaxf(p2x * SRINV, 0.f), (float)(WW-1));
    float iy = fminf(fmaxf(p2y * SRINV, 0.f), (float)(HH-1));
    BilinSetup s = bilin_setup(ix, iy);

    const float4* I1 = reinterpret_cast<const float4*>(d_img1T);
    const float4* F0 = reinterpret_cast<const float4*>(d_feat0) + (size_t)n * C4;
    int c = tid;
    float4 i00 = I1[(size_t)s.b00 + c], i10 = I1[(size_t)s.b10 + c];
    float4 i01 = I1[(size_t)s.b01 + c], i11 = I1[(size_t)s.b11 + c];
    float4 f0 = F0[c];
    float acc = 0.f;
#define PROCC(cmp) { float e = bil(i00.cmp, i10.cmp, i01.cmp, i11.cmp, s) - f0.cmp; acc += e*e; }
    PROCC(x) PROCC(y) PROCC(z) PROCC(w)
#undef PROCC
#pragma unroll
    for (int off = 16; off; off >>= 1) acc += __shfl_down_sync(0xffffffffu, acc, off);
    __shared__ float sm[8];
    int wid = tid >> 5, lane = tid & 31;
    if (lane == 0) sm[wid] = acc;
    __syncthreads();
    if (tid == 0) {
        float total = 0.f;
#pragma unroll
        for (int w = 0; w < 8; w++) total += sm[w];
        d_costpt[n] = total;
        d_candp2[2*n]   = p2x;
        d_candp2[2*n+1] = p2y;
    }
}

// ---------------- accept / reject ----------------
__global__ void __launch_bounds__(256) k_accept(int mode) {
    int tid = threadIdx.x;
    float acc = 0.f;
    for (int n = tid; n < NP; n += 256) acc += d_costpt[n];
    __shared__ float sm[256];
    sm[tid] = acc;
    __syncthreads();
    for (int sgap = 128; sgap; sgap >>= 1) {
        if (tid < sgap) sm[tid] += sm[tid + sgap];
        __syncthreads();
    }
    if (tid == 0) {
        float newc = sm[0] / (float)NP;
        if (mode == 0) {
            d_prev = newc;
            d_acc = 1.f;
        } else {
            bool a = (newc <= d_prev);
            if (a) {
#pragma unroll
                for (int i = 0; i < 9; i++) d_R[i] = d_Rc[i];
#pragma unroll
                for (int i = 0; i < 3; i++) d_t[i] = d_tc[i];
                d_prev = newc;
            }
            float l = d_lam * (a ? 0.1f : 10.f);
            d_lam = fminf(fmaxf(l, 1e-6f), 100.f);
            d_acc = a ? 1.f : 0.f;
        }
    }
}

// ---------------- conditional best copy ----------------
__global__ void k_copybest(float* __restrict__ out) {
    if (d_acc == 0.f) return;
    int n = blockIdx.x * blockDim.x + threadIdx.x;
    if (n < NP) {
        float2 v = reinterpret_cast<const float2*>(d_candp2)[n];
        reinterpret_cast<float2*>(out)[n] = v;
    }
}

// ---------------- launch ----------------
extern "C" void kernel_launch(void* const* d_in, const int* in_sizes, int n_in,
                              void* d_out, int out_size) {
    const float* imgf0 = (const float*)d_in[0];
    const float* imgf1 = (const float*)d_in[1];
    const float* pts2d = (const float*)d_in[2];
    const float* pts3d = (const float*)d_in[3];
    const float* qm    = (const float*)d_in[4];
    const float* rm    = (const float*)d_in[5];
    const float* Km    = (const float*)d_in[6];
    float* out = (float*)d_out;

    dim3 tb(32, 8);
    k_transpose<<<dim3(HW/32, CC/32), tb>>>(imgf0, 0);
    k_transpose<<<dim3(HW/32, CC/32), tb>>>(imgf1, 1);
    k_sobel<<<dim3(WW, HH), 256>>>();
    k_feat0<<<NP, 256>>>(pts2d);
    k_pts3d0<<<NP/256, 256>>>(pts3d, rm);
    k_init_state<<<1, 1>>>(qm, rm);

    // initial cost + best = pts2d_init
    k_cost<<<NP, 256>>>(Km);
    k_accept<<<1, 256>>>(0);
    k_copybest<<<NP/256, 256>>>(out);

    for (int it = 0; it < NITERS; it++) {
        k_jac<<<NP, 256>>>(Km);
        k_reduce_jac<<<1, 256>>>();
        k_solve<<<1, 1>>>();
        k_cost<<<NP, 256>>>(Km);
        k_accept<<<1, 256>>>(1);
        k_copybest<<<NP/256, 256>>>(out);
    }
}

// round 2
// speedup vs baseline: 1.2726x; 1.2726x over previous
#include <cuda_runtime.h>
#include <math.h>

#define CC 1024
#define C4 (CC/4)
#define HH 128
#define WW 128
#define HW (HH*WW)
#define NP 4096
#define SRINV 0.125f
#define NITERS 10

// ---------------- device state ----------------
__device__ float d_img0T[HW*CC];     // imgf0 [H,W,C]
__device__ float d_img1T[HW*CC];     // imgf1 [H,W,C]
__device__ float d_gT[HW*CC*2];      // sobel gx,gy interleaved per channel: [pix][c][2]
__device__ float d_feat0[NP*CC];
__device__ float d_err[2][NP*CC];    // cached err buffers (double-buffered)
__device__ float d_pts3d0[NP*3];
__device__ float d_part[27*NP];
__device__ float d_costpt[NP];
__device__ float d_candp2[NP*2];
__device__ float d_R[9];
__device__ float d_t[3];
__device__ float d_Rc[9];
__device__ float d_tc[3];
__device__ float d_lam;
__device__ float d_prev;
__device__ int   d_sel;    // which err buffer corresponds to current accepted pose
__device__ int   d_redo;   // 1 if H,g must be recomputed (pose changed)
__device__ float d_Hm[36];
__device__ float d_gv[6];

// ---------------- prep: CHW -> HWC transpose ----------------
__global__ void k_transpose(const float* __restrict__ src, int dst_sel) {
    float* dst = dst_sel ? d_img1T : d_img0T;
    __shared__ float tile[32][33];
    int hw0 = blockIdx.x * 32;
    int c0  = blockIdx.y * 32;
#pragma unroll
    for (int i = threadIdx.y; i < 32; i += 8)
        tile[i][threadIdx.x] = src[(size_t)(c0 + i) * HW + hw0 + threadIdx.x];
    __syncthreads();
#pragma unroll
    for (int i = threadIdx.y; i < 32; i += 8)
        dst[(size_t)(hw0 + i) * CC + c0 + threadIdx.x] = tile[threadIdx.x][i];
}

// ---------------- prep: sobel in HWC, interleaved gx/gy output ----------------
__global__ void __launch_bounds__(256) k_sobel() {
    int x = blockIdx.x, y = blockIdx.y;
    int c = threadIdx.x;  // float4 channel group
    const float4* img = reinterpret_cast<const float4*>(d_img1T);
    float4 v[3][3];
#pragma unroll
    for (int dy = -1; dy <= 1; dy++) {
#pragma unroll
        for (int dx = -1; dx <= 1; dx++) {
            int yy = y + dy, xx = x + dx;
            float4 val = make_float4(0.f, 0.f, 0.f, 0.f);
            if (yy >= 0 && yy < HH && xx >= 0 && xx < WW)
                val = img[(size_t)(yy * WW + xx) * C4 + c];
            v[dy+1][dx+1] = val;
        }
    }
    float4 gx, gy;
#define SOB(cmp) \
    gx.cmp = (v[0][2].cmp - v[0][0].cmp + 2.f*(v[1][2].cmp - v[1][0].cmp) + v[2][2].cmp - v[2][0].cmp) * 0.125f; \
    gy.cmp = (v[2][0].cmp - v[0][0].cmp + 2.f*(v[2][1].cmp - v[0][1].cmp) + v[2][2].cmp - v[0][2].cmp) * 0.125f;
    SOB(x) SOB(y) SOB(z) SOB(w)
#undef SOB
    // interleaved: base = pix*512 (float4 units); gx at 2c, gy at 2c+1
    size_t o = (size_t)(y * WW + x) * (C4*2) + 2*c;
    reinterpret_cast<float4*>(d_gT)[o]   = gx;
    reinterpret_cast<float4*>(d_gT)[o+1] = gy;
}

// ---------------- bilinear setup helper ----------------
struct BilinSetup {
    int b00, b10, b01, b11;   // pixel indices
    float w00, w10, w01, w11;
};
__device__ __forceinline__ BilinSetup bilin_setup(float x, float y) {
    BilinSetup s;
    float x0f = floorf(x), y0f = floorf(y);
    float wx = x - x0f, wy = y - y0f;
    int x0 = min(max((int)x0f, 0), WW-1);
    int x1 = min(max(x0 + 1, 0), WW-1);
    int y0 = min(max((int)y0f, 0), HH-1);
    int y1 = min(max(y0 + 1, 0), HH-1);
    s.w00 = (1.f-wx)*(1.f-wy); s.w10 = wx*(1.f-wy);
    s.w01 = (1.f-wx)*wy;       s.w11 = wx*wy;
    s.b00 = (y0*WW + x0); s.b10 = (y0*WW + x1);
    s.b01 = (y1*WW + x0); s.b11 = (y1*WW + x1);
    return s;
}
__device__ __forceinline__ float bil(float a, float b, float c, float d, const BilinSetup& s) {
    return a*s.w00 + b*s.w10 + c*s.w01 + d*s.w11;
}

// ---------------- prep: feat0 ----------------
__global__ void __launch_bounds__(256) k_feat0(const float* __restrict__ pts2d) {
    int n = blockIdx.x;
    BilinSetup s = bilin_setup(pts2d[2*n] * SRINV, pts2d[2*n+1] * SRINV);
    const float4* img = reinterpret_cast<const float4*>(d_img0T);
    int c = threadIdx.x;
    float4 f00 = img[(size_t)s.b00*C4 + c], f10 = img[(size_t)s.b10*C4 + c];
    float4 f01 = img[(size_t)s.b01*C4 + c], f11 = img[(size_t)s.b11*C4 + c];
    float4 o;
    o.x = bil(f00.x, f10.x, f01.x, f11.x, s);
    o.y = bil(f00.y, f10.y, f01.y, f11.y, s);
    o.z = bil(f00.z, f10.z, f01.z, f11.z, s);
    o.w = bil(f00.w, f10.w, f01.w, f11.w, s);
    reinterpret_cast<float4*>(d_feat0)[(size_t)n * C4 + c] = o;
}

// ---------------- prep: pts3d0 ----------------
__global__ void k_pts3d0(const float* __restrict__ p3d, const float* __restrict__ rm) {
    int n = blockIdx.x * blockDim.x + threadIdx.x;
    if (n >= NP) return;
    float X = p3d[3*n], Y = p3d[3*n+1], Z = p3d[3*n+2];
    float px = rm[0]*X + rm[1]*Y + rm[2]*Z + rm[3];
    float py = rm[4]*X + rm[5]*Y + rm[6]*Z + rm[7];
    float pz = rm[8]*X + rm[9]*Y + rm[10]*Z + rm[11];
    float pw = rm[12]*X + rm[13]*Y + rm[14]*Z + rm[15];
    d_pts3d0[3*n]   = px / pw;
    d_pts3d0[3*n+1] = py / pw;
    d_pts3d0[3*n+2] = pz / pw;
}

// ---------------- init: relative = q @ inv(r) ----------------
__global__ void k_init_state(const float* __restrict__ q, const float* __restrict__ r) {
    double M[4][8];
    for (int i = 0; i < 4; i++)
        for (int j = 0; j < 4; j++) { M[i][j] = r[i*4+j]; M[i][4+j] = (i == j) ? 1.0 : 0.0; }
    for (int col = 0; col < 4; col++) {
        int piv = col; double best = fabs(M[col][col]);
        for (int i = col+1; i < 4; i++) if (fabs(M[i][col]) > best) { best = fabs(M[i][col]); piv = i; }
        if (piv != col) for (int j = 0; j < 8; j++) { double tmp = M[col][j]; M[col][j] = M[piv][j]; M[piv][j] = tmp; }
        double inv = 1.0 / M[col][col];
        for (int j = 0; j < 8; j++) M[col][j] *= inv;
        for (int i = 0; i < 4; i++) if (i != col) {
            double f = M[i][col];
            for (int j = 0; j < 8; j++) M[i][j] -= f * M[col][j];
        }
    }
    for (int i = 0; i < 3; i++) {
        for (int j = 0; j < 4; j++) {
            double s = 0.0;
            for (int k = 0; k < 4; k++) s += (double)q[i*4+k] * M[k][4+j];
            if (j < 3) { d_R[i*3+j] = (float)s; d_Rc[i*3+j] = (float)s; }
            else       { d_t[i] = (float)s; d_tc[i] = (float)s; }
        }
    }
    d_lam = 0.01f;
    d_sel = 0;
    d_redo = 1;
}

// ---------------- projection helper ----------------
__device__ __forceinline__ void project_pt(int n, const float* R, const float* t,
                                           const float* __restrict__ Km,
                                           float& px, float& py, float& pz,
                                           float& p2x, float& p2y) {
    float X = d_pts3d0[3*n], Y = d_pts3d0[3*n+1], Z = d_pts3d0[3*n+2];
    px = R[0]*X + R[1]*Y + R[2]*Z + t[0];
    py = R[3]*X + R[4]*Y + R[5]*Z + t[1];
    pz = R[6]*X + R[7]*Y + R[8]*Z + t[2];
    float qx = Km[0]*px + Km[1]*py + Km[2]*pz;
    float qy = Km[3]*px + Km[4]*py + Km[5]*pz;
    float qz = Km[6]*px + Km[7]*py + Km[8]*pz;
    p2x = qx / qz; p2y = qy / qz;
}

// ---------------- Jacobian reductions per point (uses cached err) ----------------
__global__ void __launch_bounds__(256) k_jac(const float* __restrict__ Km) {
    if (d_redo == 0) return;        // pose unchanged since last H,g -> reuse
    int n = blockIdx.x;
    int tid = threadIdx.x;
    float R[9], t[3];
#pragma unroll
    for (int i = 0; i < 9; i++) R[i] = d_R[i];
#pragma unroll
    for (int i = 0; i < 3; i++) t[i] = d_t[i];
    float px, py, pz, p2x, p2y;
    project_pt(n, R, t, Km, px, py, pz, p2x, p2y);
    float ix = fminf(fmaxf(p2x * SRINV, 0.f), (float)(WW-1));
    float iy = fminf(fmaxf(p2y * SRINV, 0.f), (float)(HH-1));
    BilinSetup s = bilin_setup(ix, iy);

    const float4* G = reinterpret_cast<const float4*>(d_gT);
    const float4* E = reinterpret_cast<const float4*>(d_err[d_sel]) + (size_t)n * C4;

    int c = tid;
    size_t g00 = (size_t)s.b00*(C4*2) + 2*c, g10 = (size_t)s.b10*(C4*2) + 2*c;
    size_t g01 = (size_t)s.b01*(C4*2) + 2*c, g11 = (size_t)s.b11*(C4*2) + 2*c;
    float4 gx00 = G[g00],   gy00 = G[g00+1];
    float4 gx10 = G[g10],   gy10 = G[g10+1];
    float4 gx01 = G[g01],   gy01 = G[g01+1];
    float4 gx11 = G[g11],   gy11 = G[g11+1];
    float4 e4 = E[c];

    float sx = 0.f, sy = 0.f, sxx = 0.f, sxy = 0.f, syy = 0.f;
#define PROC(cmp) { \
    float jx = bil(gx00.cmp, gx10.cmp, gx01.cmp, gx11.cmp, s); \
    float jy = bil(gy00.cmp, gy10.cmp, gy01.cmp, gy11.cmp, s); \
    float e = e4.cmp; \
    sx += jx*e; sy += jy*e; sxx += jx*jx; sxy += jx*jy; syy += jy*jy; }
    PROC(x) PROC(y) PROC(z) PROC(w)
#undef PROC

#pragma unroll
    for (int off = 16; off; off >>= 1) {
        sx  += __shfl_down_sync(0xffffffffu, sx,  off);
        sy  += __shfl_down_sync(0xffffffffu, sy,  off);
        sxx += __shfl_down_sync(0xffffffffu, sxx, off);
        sxy += __shfl_down_sync(0xffffffffu, sxy, off);
        syy += __shfl_down_sync(0xffffffffu, syy, off);
    }
    __shared__ float sm[8][5];
    int wid = tid >> 5, lane = tid & 31;
    if (lane == 0) { sm[wid][0] = sx; sm[wid][1] = sy; sm[wid][2] = sxx; sm[wid][3] = sxy; sm[wid][4] = syy; }
    __syncthreads();
    if (tid == 0) {
        float SX = 0.f, SY = 0.f, SXX = 0.f, SXY = 0.f, SYY = 0.f;
#pragma unroll
        for (int w = 0; w < 8; w++) { SX += sm[w][0]; SY += sm[w][1]; SXX += sm[w][2]; SXY += sm[w][3]; SYY += sm[w][4]; }

        float fx = Km[0], fy = Km[4];
        float invz = 1.f / pz;
        float sc = invz * SRINV;
        float a00 = fx * sc, a01 = 0.f, a02 = -fx * px * invz * sc;
        float a10 = 0.f, a11 = fy * sc, a12 = -fy * py * invz * sc;
        float A0[6], A1[6];
        A0[0] = a00; A0[1] = a01; A0[2] = a02;
        A1[0] = a10; A1[1] = a11; A1[2] = a12;
        A0[3] = -(a01*pz - a02*py);
        A0[4] = -(-a00*pz + a02*px);
        A0[5] = -(a00*py - a01*px);
        A1[3] = -(a11*pz - a12*py);
        A1[4] = -(-a10*pz + a12*px);
        A1[5] = -(a10*py - a11*px);

#pragma unroll
        for (int k = 0; k < 6; k++)
            d_part[k*NP + n] = SX*A0[k] + SY*A1[k];
        int idx = 6;
#pragma unroll
        for (int k = 0; k < 6; k++)
#pragma unroll
            for (int l = k; l < 6; l++) {
                d_part[idx*NP + n] = SXX*A0[k]*A0[l] + SXY*(A0[k]*A1[l] + A1[k]*A0[l]) + SYY*A1[k]*A1[l];
                idx++;
            }
    }
}

// ---------------- fused: deterministic reduce of g/H + LM solve ----------------
__global__ void __launch_bounds__(256) k_reduce_solve() {
    int tid = threadIdx.x;
    if (d_redo != 0) {
        float acc[27];
#pragma unroll
        for (int k = 0; k < 27; k++) acc[k] = 0.f;
        for (int n = tid; n < NP; n += 256)
#pragma unroll
            for (int k = 0; k < 27; k++) acc[k] += d_part[k*NP + n];
        __shared__ float sm[27][256];
#pragma unroll
        for (int k = 0; k < 27; k++) sm[k][tid] = acc[k];
        __syncthreads();
        for (int sgap = 128; sgap; sgap >>= 1) {
            if (tid < sgap)
#pragma unroll
                for (int k = 0; k < 27; k++) sm[k][tid] += sm[k][tid + sgap];
            __syncthreads();
        }
        if (tid == 0) {
#pragma unroll
            for (int k = 0; k < 6; k++) d_gv[k] = sm[k][0];
            int idx = 6;
            for (int k = 0; k < 6; k++)
                for (int l = k; l < 6; l++) {
                    d_Hm[k*6+l] = sm[idx][0];
                    d_Hm[l*6+k] = sm[idx][0];
                    idx++;
                }
        }
        __syncthreads();
    }
    if (tid != 0) return;

    // ---- LM solve (fp64, single thread) ----
    double Hd[6][7];
    double lam = (double)d_lam;
    for (int k = 0; k < 6; k++) {
        for (int l = 0; l < 6; l++) Hd[k][l] = (double)d_Hm[k*6+l];
        Hd[k][k] += ((double)d_Hm[k*6+k] + 1e-9) * lam;
        Hd[k][6] = -(double)d_gv[k];
    }
    for (int col = 0; col < 6; col++) {
        int piv = col; double best = fabs(Hd[col][col]);
        for (int r = col+1; r < 6; r++) if (fabs(Hd[r][col]) > best) { best = fabs(Hd[r][col]); piv = r; }
        if (piv != col) for (int j = 0; j < 7; j++) { double tmp = Hd[col][j]; Hd[col][j] = Hd[piv][j]; Hd[piv][j] = tmp; }
        double ip = 1.0 / Hd[col][col];
        for (int r = col+1; r < 6; r++) {
            double f = Hd[r][col] * ip;
            for (int j = col; j < 7; j++) Hd[r][j] -= f * Hd[col][j];
        }
    }
    double delta[6];
    for (int r = 5; r >= 0; r--) {
        double sv = Hd[r][6];
        for (int j = r+1; j < 6; j++) sv -= Hd[r][j] * delta[j];
        delta[r] = sv / Hd[r][r];
    }
    double w0 = delta[3], w1 = delta[4], w2 = delta[5];
    double th2 = w0*w0 + w1*w1 + w2*w2;
    double th = sqrt(fmax(th2, 1e-24));
    double Ac = (th2 < 1e-16) ? 1.0 : sin(th) / th;
    double Bc = (th2 < 1e-16) ? 0.5 : (1.0 - cos(th)) / fmax(th2, 1e-24);
    double dr[3][3];
    dr[0][0] = 1.0 + Bc*(w0*w0 - th2);
    dr[0][1] = -Ac*w2 + Bc*w0*w1;
    dr[0][2] =  Ac*w1 + Bc*w0*w2;
    dr[1][0] =  Ac*w2 + Bc*w1*w0;
    dr[1][1] = 1.0 + Bc*(w1*w1 - th2);
    dr[1][2] = -Ac*w0 + Bc*w1*w2;
    dr[2][0] = -Ac*w1 + Bc*w2*w0;
    dr[2][1] =  Ac*w0 + Bc*w2*w1;
    dr[2][2] = 1.0 + Bc*(w2*w2 - th2);
    for (int i = 0; i < 3; i++) {
        for (int j = 0; j < 3; j++) {
            double sv = 0.0;
            for (int k = 0; k < 3; k++) sv += dr[i][k] * (double)d_R[k*3+j];
            d_Rc[i*3+j] = (float)sv;
        }
        double sv = delta[i];
        for (int k = 0; k < 3; k++) sv += dr[i][k] * (double)d_t[k];
        d_tc[i] = (float)sv;
    }
}

// ---------------- candidate cost per point (+ err caching) ----------------
__global__ void __launch_bounds__(256) k_cost(const float* __restrict__ Km) {
    int n = blockIdx.x;
    int tid = threadIdx.x;
    int wbuf = d_sel ^ 1;
    float R[9], t[3];
#pragma unroll
    for (int i = 0; i < 9; i++) R[i] = d_Rc[i];
#pragma unroll
    for (int i = 0; i < 3; i++) t[i] = d_tc[i];
    float px, py, pz, p2x, p2y;
    project_pt(n, R, t, Km, px, py, pz, p2x, p2y);
    float ix = fminf(fmaxf(p2x * SRINV, 0.f), (float)(WW-1));
    float iy = fminf(fmaxf(p2y * SRINV, 0.f), (float)(HH-1));
    BilinSetup s = bilin_setup(ix, iy);

    const float4* I1 = reinterpret_cast<const float4*>(d_img1T);
    const float4* F0 = reinterpret_cast<const float4*>(d_feat0) + (size_t)n * C4;
    int c = tid;
    float4 i00 = I1[(size_t)s.b00*C4 + c], i10 = I1[(size_t)s.b10*C4 + c];
    float4 i01 = I1[(size_t)s.b01*C4 + c], i11 = I1[(size_t)s.b11*C4 + c];
    float4 f0 = F0[c];
    float4 e4;
    float acc = 0.f;
#define PROCC(cmp) { float e = bil(i00.cmp, i10.cmp, i01.cmp, i11.cmp, s) - f0.cmp; e4.cmp = e; acc += e*e; }
    PROCC(x) PROCC(y) PROCC(z) PROCC(w)
#undef PROCC
    reinterpret_cast<float4*>(d_err[wbuf])[(size_t)n * C4 + c] = e4;
#pragma unroll
    for (int off = 16; off; off >>= 1) acc += __shfl_down_sync(0xffffffffu, acc, off);
    __shared__ float sm[8];
    int wid = tid >> 5, lane = tid & 31;
    if (lane == 0) sm[wid] = acc;
    __syncthreads();
    if (tid == 0) {
        float total = 0.f;
#pragma unroll
        for (int w = 0; w < 8; w++) total += sm[w];
        d_costpt[n] = total;
        d_candp2[2*n]   = p2x;
        d_candp2[2*n+1] = p2y;
    }
}

// ---------------- fused: accept/reject + best copy ----------------
__global__ void __launch_bounds__(256) k_accept_copy(int mode, float* __restrict__ out) {
    int tid = threadIdx.x;
    float acc = 0.f;
    for (int n = tid; n < NP; n += 256) acc += d_costpt[n];
    __shared__ float sm[256];
    __shared__ int s_acc;
    sm[tid] = acc;
    __syncthreads();
    for (int sgap = 128; sgap; sgap >>= 1) {
        if (tid < sgap) sm[tid] += sm[tid + sgap];
        __syncthreads();
    }
    if (tid == 0) {
        float newc = sm[0] / (float)NP;
        if (mode == 0) {
            d_prev = newc;
            d_sel = 1;      // initial err written to buf 1
            d_redo = 1;
            s_acc = 1;
        } else {
            bool a = (newc <= d_prev);
            if (a) {
#pragma unroll
                for (int i = 0; i < 9; i++) d_R[i] = d_Rc[i];
#pragma unroll
                for (int i = 0; i < 3; i++) d_t[i] = d_tc[i];
                d_prev = newc;
                d_sel ^= 1;
            }
            d_redo = a ? 1 : 0;
            float l = d_lam * (a ? 0.1f : 10.f);
            d_lam = fminf(fmaxf(l, 1e-6f), 100.f);
            s_acc = a ? 1 : 0;
        }
    }
    __syncthreads();
    if (s_acc) {
        const float2* src = reinterpret_cast<const float2*>(d_candp2);
        float2* dst = reinterpret_cast<float2*>(out);
        for (int n = tid; n < NP; n += 256) dst[n] = src[n];
    }
}

// ---------------- launch ----------------
extern "C" void kernel_launch(void* const* d_in, const int* in_sizes, int n_in,
                              void* d_out, int out_size) {
    const float* imgf0 = (const float*)d_in[0];
    const float* imgf1 = (const float*)d_in[1];
    const float* pts2d = (const float*)d_in[2];
    const float* pts3d = (const float*)d_in[3];
    const float* qm    = (const float*)d_in[4];
    const float* rm    = (const float*)d_in[5];
    const float* Km    = (const float*)d_in[6];
    float* out = (float*)d_out;

    dim3 tb(32, 8);
    k_transpose<<<dim3(HW/32, CC/32), tb>>>(imgf0, 0);
    k_transpose<<<dim3(HW/32, CC/32), tb>>>(imgf1, 1);
    k_sobel<<<dim3(WW, HH), 256>>>();
    k_feat0<<<NP, 256>>>(pts2d);
    k_pts3d0<<<NP/256, 256>>>(pts3d, rm);
    k_init_state<<<1, 1>>>(qm, rm);

    // initial cost at init pose: d_Rc/d_tc == init pose after k_init_state
    k_cost<<<NP, 256>>>(Km);
    k_accept_copy<<<1, 256>>>(0, out);

    for (int it = 0; it < NITERS; it++) {
        k_jac<<<NP, 256>>>(Km);
        k_reduce_solve<<<1, 256>>>();
        k_cost<<<NP, 256>>>(Km);
        k_accept_copy<<<1, 256>>>(1, out);
    }
}

// round 3
// speedup vs baseline: 1.4004x; 1.1004x over previous
#include <cuda_runtime.h>
#include <cuda_bf16.h>
#include <math.h>

#define CC 1024
#define C4 (CC/4)
#define HH 128
#define WW 128
#define HW (HH*WW)
#define NP 4096
#define SRINV 0.125f
#define NITERS 10

// ---------------- device state ----------------
__device__ float d_img0T[HW*CC];                 // imgf0 [H,W,C] fp32
__device__ float d_img1T[HW*CC];                 // imgf1 [H,W,C] fp32
__device__ __nv_bfloat16 d_gT[HW*CC*2];          // packed bf16: per pix, per c4: {gx0..3, gy0..3}
__device__ float d_feat0[NP*CC];
__device__ float d_errbuf[2][NP*CC];             // cached err (double-buffered)
__device__ float d_pts3d0[NP*3];
__device__ float d_part[27*NP];
__device__ float d_costpt[NP];
__device__ float d_candp2[NP*2];
__device__ float d_R[9];
__device__ float d_t[3];
__device__ float d_Rc[9];
__device__ float d_tc[3];
__device__ float d_lam;
__device__ float d_prev;
__device__ int   d_sel;
__device__ int   d_redo;
__device__ float d_Hm[36];
__device__ float d_gv[6];

// ---------------- prep: CHW -> HWC transpose ----------------
__global__ void k_transpose(const float* __restrict__ src, int dst_sel) {
    float* dst = dst_sel ? d_img1T : d_img0T;
    __shared__ float tile[32][33];
    int hw0 = blockIdx.x * 32;
    int c0  = blockIdx.y * 32;
#pragma unroll
    for (int i = threadIdx.y; i < 32; i += 8)
        tile[i][threadIdx.x] = src[(size_t)(c0 + i) * HW + hw0 + threadIdx.x];
    __syncthreads();
#pragma unroll
    for (int i = threadIdx.y; i < 32; i += 8)
        dst[(size_t)(hw0 + i) * CC + c0 + threadIdx.x] = tile[threadIdx.x][i];
}

// ---------------- prep: sobel in HWC, bf16 packed output ----------------
__global__ void __launch_bounds__(256) k_sobel() {
    int x = blockIdx.x, y = blockIdx.y;
    int c = threadIdx.x;  // float4 channel group
    const float4* img = reinterpret_cast<const float4*>(d_img1T);
    float4 v[3][3];
#pragma unroll
    for (int dy = -1; dy <= 1; dy++) {
#pragma unroll
        for (int dx = -1; dx <= 1; dx++) {
            int yy = y + dy, xx = x + dx;
            float4 val = make_float4(0.f, 0.f, 0.f, 0.f);
            if (yy >= 0 && yy < HH && xx >= 0 && xx < WW)
                val = img[(size_t)(yy * WW + xx) * C4 + c];
            v[dy+1][dx+1] = val;
        }
    }
    float4 gx, gy;
#define SOB(cmp) \
    gx.cmp = (v[0][2].cmp - v[0][0].cmp + 2.f*(v[1][2].cmp - v[1][0].cmp) + v[2][2].cmp - v[2][0].cmp) * 0.125f; \
    gy.cmp = (v[2][0].cmp - v[0][0].cmp + 2.f*(v[2][1].cmp - v[0][1].cmp) + v[2][2].cmp - v[0][2].cmp) * 0.125f;
    SOB(x) SOB(y) SOB(z) SOB(w)
#undef SOB
    __nv_bfloat162 p0 = __floats2bfloat162_rn(gx.x, gx.y);
    __nv_bfloat162 p1 = __floats2bfloat162_rn(gx.z, gx.w);
    __nv_bfloat162 p2 = __floats2bfloat162_rn(gy.x, gy.y);
    __nv_bfloat162 p3 = __floats2bfloat162_rn(gy.z, gy.w);
    uint4 o;
    o.x = *reinterpret_cast<unsigned*>(&p0);
    o.y = *reinterpret_cast<unsigned*>(&p1);
    o.z = *reinterpret_cast<unsigned*>(&p2);
    o.w = *reinterpret_cast<unsigned*>(&p3);
    reinterpret_cast<uint4*>(d_gT)[(size_t)(y * WW + x) * C4 + c] = o;
}

// ---------------- bilinear setup ----------------
struct BilinSetup {
    int b00, b10, b01, b11;   // pixel indices
    float w00, w10, w01, w11;
};
__device__ __forceinline__ BilinSetup bilin_setup(float x, float y) {
    BilinSetup s;
    float x0f = floorf(x), y0f = floorf(y);
    float wx = x - x0f, wy = y - y0f;
    int x0 = min(max((int)x0f, 0), WW-1);
    int x1 = min(max(x0 + 1, 0), WW-1);
    int y0 = min(max((int)y0f, 0), HH-1);
    int y1 = min(max(y0 + 1, 0), HH-1);
    s.w00 = (1.f-wx)*(1.f-wy); s.w10 = wx*(1.f-wy);
    s.w01 = (1.f-wx)*wy;       s.w11 = wx*wy;
    s.b00 = (y0*WW + x0); s.b10 = (y0*WW + x1);
    s.b01 = (y1*WW + x0); s.b11 = (y1*WW + x1);
    return s;
}
__device__ __forceinline__ float bil(float a, float b, float c, float d, const BilinSetup& s) {
    return a*s.w00 + b*s.w10 + c*s.w01 + d*s.w11;
}

// ---------------- prep: feat0 ----------------
__global__ void __launch_bounds__(256) k_feat0(const float* __restrict__ pts2d) {
    int n = blockIdx.x;
    BilinSetup s = bilin_setup(pts2d[2*n] * SRINV, pts2d[2*n+1] * SRINV);
    const float4* img = reinterpret_cast<const float4*>(d_img0T);
    int c = threadIdx.x;
    float4 f00 = img[(size_t)s.b00*C4 + c], f10 = img[(size_t)s.b10*C4 + c];
    float4 f01 = img[(size_t)s.b01*C4 + c], f11 = img[(size_t)s.b11*C4 + c];
    float4 o;
    o.x = bil(f00.x, f10.x, f01.x, f11.x, s);
    o.y = bil(f00.y, f10.y, f01.y, f11.y, s);
    o.z = bil(f00.z, f10.z, f01.z, f11.z, s);
    o.w = bil(f00.w, f10.w, f01.w, f11.w, s);
    reinterpret_cast<float4*>(d_feat0)[(size_t)n * C4 + c] = o;
}

// ---------------- prep: pts3d0 ----------------
__global__ void k_pts3d0(const float* __restrict__ p3d, const float* __restrict__ rm) {
    int n = blockIdx.x * blockDim.x + threadIdx.x;
    if (n >= NP) return;
    float X = p3d[3*n], Y = p3d[3*n+1], Z = p3d[3*n+2];
    float px = rm[0]*X + rm[1]*Y + rm[2]*Z + rm[3];
    float py = rm[4]*X + rm[5]*Y + rm[6]*Z + rm[7];
    float pz = rm[8]*X + rm[9]*Y + rm[10]*Z + rm[11];
    float pw = rm[12]*X + rm[13]*Y + rm[14]*Z + rm[15];
    d_pts3d0[3*n]   = px / pw;
    d_pts3d0[3*n+1] = py / pw;
    d_pts3d0[3*n+2] = pz / pw;
}

// ---------------- init: relative = q @ inv(r) ----------------
__global__ void k_init_state(const float* __restrict__ q, const float* __restrict__ r) {
    double M[4][8];
    for (int i = 0; i < 4; i++)
        for (int j = 0; j < 4; j++) { M[i][j] = r[i*4+j]; M[i][4+j] = (i == j) ? 1.0 : 0.0; }
    for (int col = 0; col < 4; col++) {
        int piv = col; double best = fabs(M[col][col]);
        for (int i = col+1; i < 4; i++) if (fabs(M[i][col]) > best) { best = fabs(M[i][col]); piv = i; }
        if (piv != col) for (int j = 0; j < 8; j++) { double tmp = M[col][j]; M[col][j] = M[piv][j]; M[piv][j] = tmp; }
        double inv = 1.0 / M[col][col];
        for (int j = 0; j < 8; j++) M[col][j] *= inv;
        for (int i = 0; i < 4; i++) if (i != col) {
            double f = M[i][col];
            for (int j = 0; j < 8; j++) M[i][j] -= f * M[col][j];
        }
    }
    for (int i = 0; i < 3; i++) {
        for (int j = 0; j < 4; j++) {
            double s = 0.0;
            for (int k = 0; k < 4; k++) s += (double)q[i*4+k] * M[k][4+j];
            if (j < 3) { d_R[i*3+j] = (float)s; d_Rc[i*3+j] = (float)s; }
            else       { d_t[i] = (float)s; d_tc[i] = (float)s; }
        }
    }
    d_lam = 0.01f;
    d_sel = 0;
    d_redo = 1;
}

// ---------------- projection helper ----------------
__device__ __forceinline__ void project_pt(int n, const float* R, const float* t,
                                           const float* __restrict__ Km,
                                           float& px, float& py, float& pz,
                                           float& p2x, float& p2y) {
    float X = d_pts3d0[3*n], Y = d_pts3d0[3*n+1], Z = d_pts3d0[3*n+2];
    px = R[0]*X + R[1]*Y + R[2]*Z + t[0];
    py = R[3]*X + R[4]*Y + R[5]*Z + t[1];
    pz = R[6]*X + R[7]*Y + R[8]*Z + t[2];
    float qx = Km[0]*px + Km[1]*py + Km[2]*pz;
    float qy = Km[3]*px + Km[4]*py + Km[5]*pz;
    float qz = Km[6]*px + Km[7]*py + Km[8]*pz;
    p2x = qx / qz; p2y = qy / qz;
}

// unpack 4-channel packed bf16 gradient word
__device__ __forceinline__ void unpack_g(uint4 q, float gx[4], float gy[4]) {
    float2 a = __bfloat1622float2(*reinterpret_cast<__nv_bfloat162*>(&q.x));
    float2 b = __bfloat1622float2(*reinterpret_cast<__nv_bfloat162*>(&q.y));
    float2 c = __bfloat1622float2(*reinterpret_cast<__nv_bfloat162*>(&q.z));
    float2 d = __bfloat1622float2(*reinterpret_cast<__nv_bfloat162*>(&q.w));
    gx[0] = a.x; gx[1] = a.y; gx[2] = b.x; gx[3] = b.y;
    gy[0] = c.x; gy[1] = c.y; gy[2] = d.x; gy[3] = d.y;
}

// ---------------- Jacobian reductions per point (bf16 grads + cached err) ----------------
__global__ void __launch_bounds__(256) k_jac(const float* __restrict__ Km) {
    if (d_redo == 0) return;
    int n = blockIdx.x;
    int tid = threadIdx.x;
    float R[9], t[3];
#pragma unroll
    for (int i = 0; i < 9; i++) R[i] = d_R[i];
#pragma unroll
    for (int i = 0; i < 3; i++) t[i] = d_t[i];
    float px, py, pz, p2x, p2y;
    project_pt(n, R, t, Km, px, py, pz, p2x, p2y);
    float ix = fminf(fmaxf(p2x * SRINV, 0.f), (float)(WW-1));
    float iy = fminf(fmaxf(p2y * SRINV, 0.f), (float)(HH-1));
    BilinSetup s = bilin_setup(ix, iy);

    const uint4* G = reinterpret_cast<const uint4*>(d_gT);
    const float4* E = reinterpret_cast<const float4*>(d_errbuf[d_sel]) + (size_t)n * C4;

    int c = tid;
    uint4 q00 = G[(size_t)s.b00*C4 + c];
    uint4 q10 = G[(size_t)s.b10*C4 + c];
    uint4 q01 = G[(size_t)s.b01*C4 + c];
    uint4 q11 = G[(size_t)s.b11*C4 + c];
    float4 e4 = E[c];

    float gx00[4], gy00[4], gx10[4], gy10[4], gx01[4], gy01[4], gx11[4], gy11[4];
    unpack_g(q00, gx00, gy00);
    unpack_g(q10, gx10, gy10);
    unpack_g(q01, gx01, gy01);
    unpack_g(q11, gx11, gy11);
    float ev[4] = { e4.x, e4.y, e4.z, e4.w };

    float sx = 0.f, sy = 0.f, sxx = 0.f, sxy = 0.f, syy = 0.f;
#pragma unroll
    for (int j = 0; j < 4; j++) {
        float jx = bil(gx00[j], gx10[j], gx01[j], gx11[j], s);
        float jy = bil(gy00[j], gy10[j], gy01[j], gy11[j], s);
        float e = ev[j];
        sx += jx*e; sy += jy*e; sxx += jx*jx; sxy += jx*jy; syy += jy*jy;
    }

#pragma unroll
    for (int off = 16; off; off >>= 1) {
        sx  += __shfl_down_sync(0xffffffffu, sx,  off);
        sy  += __shfl_down_sync(0xffffffffu, sy,  off);
        sxx += __shfl_down_sync(0xffffffffu, sxx, off);
        sxy += __shfl_down_sync(0xffffffffu, sxy, off);
        syy += __shfl_down_sync(0xffffffffu, syy, off);
    }
    __shared__ float sm[8][5];
    int wid = tid >> 5, lane = tid & 31;
    if (lane == 0) { sm[wid][0] = sx; sm[wid][1] = sy; sm[wid][2] = sxx; sm[wid][3] = sxy; sm[wid][4] = syy; }
    __syncthreads();
    if (tid == 0) {
        float SX = 0.f, SY = 0.f, SXX = 0.f, SXY = 0.f, SYY = 0.f;
#pragma unroll
        for (int w = 0; w < 8; w++) { SX += sm[w][0]; SY += sm[w][1]; SXX += sm[w][2]; SXY += sm[w][3]; SYY += sm[w][4]; }

        float fx = Km[0], fy = Km[4];
        float invz = 1.f / pz;
        float sc = invz * SRINV;
        float a00 = fx * sc, a01 = 0.f, a02 = -fx * px * invz * sc;
        float a10 = 0.f, a11 = fy * sc, a12 = -fy * py * invz * sc;
        float A0[6], A1[6];
        A0[0] = a00; A0[1] = a01; A0[2] = a02;
        A1[0] = a10; A1[1] = a11; A1[2] = a12;
        A0[3] = -(a01*pz - a02*py);
        A0[4] = -(-a00*pz + a02*px);
        A0[5] = -(a00*py - a01*px);
        A1[3] = -(a11*pz - a12*py);
        A1[4] = -(-a10*pz + a12*px);
        A1[5] = -(a10*py - a11*px);

#pragma unroll
        for (int k = 0; k < 6; k++)
            d_part[k*NP + n] = SX*A0[k] + SY*A1[k];
        int idx = 6;
#pragma unroll
        for (int k = 0; k < 6; k++)
#pragma unroll
            for (int l = k; l < 6; l++) {
                d_part[idx*NP + n] = SXX*A0[k]*A0[l] + SXY*(A0[k]*A1[l] + A1[k]*A0[l]) + SYY*A1[k]*A1[l];
                idx++;
            }
    }
}

// ---------------- fused: reduce g/H + LM solve ----------------
__global__ void __launch_bounds__(256) k_reduce_solve() {
    int tid = threadIdx.x;
    if (d_redo != 0) {
        float acc[27];
#pragma unroll
        for (int k = 0; k < 27; k++) acc[k] = 0.f;
        for (int n = tid; n < NP; n += 256)
#pragma unroll
            for (int k = 0; k < 27; k++) acc[k] += d_part[k*NP + n];
        __shared__ float sm[27][256];
#pragma unroll
        for (int k = 0; k < 27; k++) sm[k][tid] = acc[k];
        __syncthreads();
        for (int sgap = 128; sgap; sgap >>= 1) {
            if (tid < sgap)
#pragma unroll
                for (int k = 0; k < 27; k++) sm[k][tid] += sm[k][tid + sgap];
            __syncthreads();
        }
        if (tid == 0) {
#pragma unroll
            for (int k = 0; k < 6; k++) d_gv[k] = sm[k][0];
            int idx = 6;
            for (int k = 0; k < 6; k++)
                for (int l = k; l < 6; l++) {
                    d_Hm[k*6+l] = sm[idx][0];
                    d_Hm[l*6+k] = sm[idx][0];
                    idx++;
                }
        }
        __syncthreads();
    }
    if (tid != 0) return;

    double Hd[6][7];
    double lam = (double)d_lam;
    for (int k = 0; k < 6; k++) {
        for (int l = 0; l < 6; l++) Hd[k][l] = (double)d_Hm[k*6+l];
        Hd[k][k] += ((double)d_Hm[k*6+k] + 1e-9) * lam;
        Hd[k][6] = -(double)d_gv[k];
    }
    for (int col = 0; col < 6; col++) {
        int piv = col; double best = fabs(Hd[col][col]);
        for (int r = col+1; r < 6; r++) if (fabs(Hd[r][col]) > best) { best = fabs(Hd[r][col]); piv = r; }
        if (piv != col) for (int j = 0; j < 7; j++) { double tmp = Hd[col][j]; Hd[col][j] = Hd[piv][j]; Hd[piv][j] = tmp; }
        double ip = 1.0 / Hd[col][col];
        for (int r = col+1; r < 6; r++) {
            double f = Hd[r][col] * ip;
            for (int j = col; j < 7; j++) Hd[r][j] -= f * Hd[col][j];
        }
    }
    double delta[6];
    for (int r = 5; r >= 0; r--) {
        double sv = Hd[r][6];
        for (int j = r+1; j < 6; j++) sv -= Hd[r][j] * delta[j];
        delta[r] = sv / Hd[r][r];
    }
    double w0 = delta[3], w1 = delta[4], w2 = delta[5];
    double th2 = w0*w0 + w1*w1 + w2*w2;
    double th = sqrt(fmax(th2, 1e-24));
    double Ac = (th2 < 1e-16) ? 1.0 : sin(th) / th;
    double Bc = (th2 < 1e-16) ? 0.5 : (1.0 - cos(th)) / fmax(th2, 1e-24);
    double dr[3][3];
    dr[0][0] = 1.0 + Bc*(w0*w0 - th2);
    dr[0][1] = -Ac*w2 + Bc*w0*w1;
    dr[0][2] =  Ac*w1 + Bc*w0*w2;
    dr[1][0] =  Ac*w2 + Bc*w1*w0;
    dr[1][1] = 1.0 + Bc*(w1*w1 - th2);
    dr[1][2] = -Ac*w0 + Bc*w1*w2;
    dr[2][0] = -Ac*w1 + Bc*w2*w0;
    dr[2][1] =  Ac*w0 + Bc*w2*w1;
    dr[2][2] = 1.0 + Bc*(w2*w2 - th2);
    for (int i = 0; i < 3; i++) {
        for (int j = 0; j < 3; j++) {
            double sv = 0.0;
            for (int k = 0; k < 3; k++) sv += dr[i][k] * (double)d_R[k*3+j];
            d_Rc[i*3+j] = (float)sv;
        }
        double sv = delta[i];
        for (int k = 0; k < 3; k++) sv += dr[i][k] * (double)d_t[k];
        d_tc[i] = (float)sv;
    }
}

// ---------------- candidate cost per point (+ err caching) ----------------
__global__ void __launch_bounds__(256) k_cost(const float* __restrict__ Km) {
    int n = blockIdx.x;
    int tid = threadIdx.x;
    int wbuf = d_sel ^ 1;
    float R[9], t[3];
#pragma unroll
    for (int i = 0; i < 9; i++) R[i] = d_Rc[i];
#pragma unroll
    for (int i = 0; i < 3; i++) t[i] = d_tc[i];
    float px, py, pz, p2x, p2y;
    project_pt(n, R, t, Km, px, py, pz, p2x, p2y);
    float ix = fminf(fmaxf(p2x * SRINV, 0.f), (float)(WW-1));
    float iy = fminf(fmaxf(p2y * SRINV, 0.f), (float)(HH-1));
    BilinSetup s = bilin_setup(ix, iy);

    const float4* I1 = reinterpret_cast<const float4*>(d_img1T);
    const float4* F0 = reinterpret_cast<const float4*>(d_feat0) + (size_t)n * C4;
    int c = tid;
    float4 i00 = I1[(size_t)s.b00*C4 + c], i10 = I1[(size_t)s.b10*C4 + c];
    float4 i01 = I1[(size_t)s.b01*C4 + c], i11 = I1[(size_t)s.b11*C4 + c];
    float4 f0 = F0[c];
    float4 e4;
    float acc = 0.f;
#define PROCC(cmp) { float e = bil(i00.cmp, i10.cmp, i01.cmp, i11.cmp, s) - f0.cmp; e4.cmp = e; acc += e*e; }
    PROCC(x) PROCC(y) PROCC(z) PROCC(w)
#undef PROCC
    reinterpret_cast<float4*>(d_errbuf[wbuf])[(size_t)n * C4 + c] = e4;
#pragma unroll
    for (int off = 16; off; off >>= 1) acc += __shfl_down_sync(0xffffffffu, acc, off);
    __shared__ float sm[8];
    int wid = tid >> 5, lane = tid & 31;
    if (lane == 0) sm[wid] = acc;
    __syncthreads();
    if (tid == 0) {
        float total = 0.f;
#pragma unroll
        for (int w = 0; w < 8; w++) total += sm[w];
        d_costpt[n] = total;
        d_candp2[2*n]   = p2x;
        d_candp2[2*n+1] = p2y;
    }
}

// ---------------- fused: accept/reject + best copy ----------------
__global__ void __launch_bounds__(256) k_accept_copy(int mode, float* __restrict__ out) {
    int tid = threadIdx.x;
    float acc = 0.f;
    for (int n = tid; n < NP; n += 256) acc += d_costpt[n];
    __shared__ float sm[256];
    __shared__ int s_acc;
    sm[tid] = acc;
    __syncthreads();
    for (int sgap = 128; sgap; sgap >>= 1) {
        if (tid < sgap) sm[tid] += sm[tid + sgap];
        __syncthreads();
    }
    if (tid == 0) {
        float newc = sm[0] / (float)NP;
        if (mode == 0) {
            d_prev = newc;
            d_sel = 1;
            d_redo = 1;
            s_acc = 1;
        } else {
            bool a = (newc <= d_prev);
            if (a) {
#pragma unroll
                for (int i = 0; i < 9; i++) d_R[i] = d_Rc[i];
#pragma unroll
                for (int i = 0; i < 3; i++) d_t[i] = d_tc[i];
                d_prev = newc;
                d_sel ^= 1;
            }
            d_redo = a ? 1 : 0;
            float l = d_lam * (a ? 0.1f : 10.f);
            d_lam = fminf(fmaxf(l, 1e-6f), 100.f);
            s_acc = a ? 1 : 0;
        }
    }
    __syncthreads();
    if (s_acc) {
        const float2* src = reinterpret_cast<const float2*>(d_candp2);
        float2* dst = reinterpret_cast<float2*>(out);
        for (int n = tid; n < NP; n += 256) dst[n] = src[n];
    }
}

// ---------------- launch ----------------
extern "C" void kernel_launch(void* const* d_in, const int* in_sizes, int n_in,
                              void* d_out, int out_size) {
    const float* imgf0 = (const float*)d_in[0];
    const float* imgf1 = (const float*)d_in[1];
    const float* pts2d = (const float*)d_in[2];
    const float* pts3d = (const float*)d_in[3];
    const float* qm    = (const float*)d_in[4];
    const float* rm    = (const float*)d_in[5];
    const float* Km    = (const float*)d_in[6];
    float* out = (float*)d_out;

    dim3 tb(32, 8);
    k_transpose<<<dim3(HW/32, CC/32), tb>>>(imgf0, 0);
    k_transpose<<<dim3(HW/32, CC/32), tb>>>(imgf1, 1);
    k_sobel<<<dim3(WW, HH), 256>>>();
    k_feat0<<<NP, 256>>>(pts2d);
    k_pts3d0<<<NP/256, 256>>>(pts3d, rm);
    k_init_state<<<1, 1>>>(qm, rm);

    k_cost<<<NP, 256>>>(Km);
    k_accept_copy<<<1, 256>>>(0, out);

    for (int it = 0; it < NITERS; it++) {
        k_jac<<<NP, 256>>>(Km);
        k_reduce_solve<<<1, 256>>>();
        k_cost<<<NP, 256>>>(Km);
        k_accept_copy<<<1, 256>>>(1, out);
    }
}

// round 4
// speedup vs baseline: 1.7123x; 1.2227x over previous
#include <cuda_runtime.h>
#include <cuda_bf16.h>
#include <math.h>

#define CC 1024
#define C4 (CC/4)
#define HH 128
#define WW 128
#define HW (HH*WW)
#define NP 4096
#define SRINV 0.125f
#define NITERS 10

// ---------------- device state ----------------
__device__ float d_img0T[HW*CC];                 // imgf0 [H,W,C] fp32
__device__ float d_img1T[HW*CC];                 // imgf1 [H,W,C] fp32
__device__ __nv_bfloat16 d_gT[HW*CC*2];          // packed bf16 per pix/c4: {gx0..3, gy0..3}
__device__ float d_feat0[NP*CC];
__device__ float d_pts3d0[NP*3];
__device__ float d_part[2][27*NP];               // per-point partials, double-buffered
__device__ float d_costpt[NP];
__device__ float d_candp2[NP*2];
__device__ float d_R[9];
__device__ float d_t[3];
__device__ float d_Rc[9];
__device__ float d_tc[3];
__device__ float d_lam;
__device__ float d_prev;
__device__ int   d_sel;    // which partial buffer is the accepted one
__device__ int   d_redo;   // 1 if H,g must be re-reduced (accepted pose changed)
__device__ float d_Hm[36];
__device__ float d_gv[6];

// ---------------- prep: CHW -> HWC transpose ----------------
__global__ void k_transpose(const float* __restrict__ src, int dst_sel) {
    float* dst = dst_sel ? d_img1T : d_img0T;
    __shared__ float tile[32][33];
    int hw0 = blockIdx.x * 32;
    int c0  = blockIdx.y * 32;
#pragma unroll
    for (int i = threadIdx.y; i < 32; i += 8)
        tile[i][threadIdx.x] = src[(size_t)(c0 + i) * HW + hw0 + threadIdx.x];
    __syncthreads();
#pragma unroll
    for (int i = threadIdx.y; i < 32; i += 8)
        dst[(size_t)(hw0 + i) * CC + c0 + threadIdx.x] = tile[threadIdx.x][i];
}

// ---------------- prep: sobel in HWC, bf16 packed output ----------------
__global__ void __launch_bounds__(256) k_sobel() {
    int x = blockIdx.x, y = blockIdx.y;
    int c = threadIdx.x;
    const float4* img = reinterpret_cast<const float4*>(d_img1T);
    float4 v[3][3];
#pragma unroll
    for (int dy = -1; dy <= 1; dy++) {
#pragma unroll
        for (int dx = -1; dx <= 1; dx++) {
            int yy = y + dy, xx = x + dx;
            float4 val = make_float4(0.f, 0.f, 0.f, 0.f);
            if (yy >= 0 && yy < HH && xx >= 0 && xx < WW)
                val = img[(size_t)(yy * WW + xx) * C4 + c];
            v[dy+1][dx+1] = val;
        }
    }
    float4 gx, gy;
#define SOB(cmp) \
    gx.cmp = (v[0][2].cmp - v[0][0].cmp + 2.f*(v[1][2].cmp - v[1][0].cmp) + v[2][2].cmp - v[2][0].cmp) * 0.125f; \
    gy.cmp = (v[2][0].cmp - v[0][0].cmp + 2.f*(v[2][1].cmp - v[0][1].cmp) + v[2][2].cmp - v[0][2].cmp) * 0.125f;
    SOB(x) SOB(y) SOB(z) SOB(w)
#undef SOB
    __nv_bfloat162 p0 = __floats2bfloat162_rn(gx.x, gx.y);
    __nv_bfloat162 p1 = __floats2bfloat162_rn(gx.z, gx.w);
    __nv_bfloat162 p2 = __floats2bfloat162_rn(gy.x, gy.y);
    __nv_bfloat162 p3 = __floats2bfloat162_rn(gy.z, gy.w);
    uint4 o;
    o.x = *reinterpret_cast<unsigned*>(&p0);
    o.y = *reinterpret_cast<unsigned*>(&p1);
    o.z = *reinterpret_cast<unsigned*>(&p2);
    o.w = *reinterpret_cast<unsigned*>(&p3);
    reinterpret_cast<uint4*>(d_gT)[(size_t)(y * WW + x) * C4 + c] = o;
}

// ---------------- bilinear setup ----------------
struct BilinSetup {
    int b00, b10, b01, b11;
    float w00, w10, w01, w11;
};
__device__ __forceinline__ BilinSetup bilin_setup(float x, float y) {
    BilinSetup s;
    float x0f = floorf(x), y0f = floorf(y);
    float wx = x - x0f, wy = y - y0f;
    int x0 = min(max((int)x0f, 0), WW-1);
    int x1 = min(max(x0 + 1, 0), WW-1);
    int y0 = min(max((int)y0f, 0), HH-1);
    int y1 = min(max(y0 + 1, 0), HH-1);
    s.w00 = (1.f-wx)*(1.f-wy); s.w10 = wx*(1.f-wy);
    s.w01 = (1.f-wx)*wy;       s.w11 = wx*wy;
    s.b00 = (y0*WW + x0); s.b10 = (y0*WW + x1);
    s.b01 = (y1*WW + x0); s.b11 = (y1*WW + x1);
    return s;
}
__device__ __forceinline__ float bil(float a, float b, float c, float d, const BilinSetup& s) {
    return a*s.w00 + b*s.w10 + c*s.w01 + d*s.w11;
}

// ---------------- prep: feat0 ----------------
__global__ void __launch_bounds__(256) k_feat0(const float* __restrict__ pts2d) {
    int n = blockIdx.x;
    BilinSetup s = bilin_setup(pts2d[2*n] * SRINV, pts2d[2*n+1] * SRINV);
    const float4* img = reinterpret_cast<const float4*>(d_img0T);
    int c = threadIdx.x;
    float4 f00 = img[(size_t)s.b00*C4 + c], f10 = img[(size_t)s.b10*C4 + c];
    float4 f01 = img[(size_t)s.b01*C4 + c], f11 = img[(size_t)s.b11*C4 + c];
    float4 o;
    o.x = bil(f00.x, f10.x, f01.x, f11.x, s);
    o.y = bil(f00.y, f10.y, f01.y, f11.y, s);
    o.z = bil(f00.z, f10.z, f01.z, f11.z, s);
    o.w = bil(f00.w, f10.w, f01.w, f11.w, s);
    reinterpret_cast<float4*>(d_feat0)[(size_t)n * C4 + c] = o;
}

// ---------------- prep: pts3d0 ----------------
__global__ void k_pts3d0(const float* __restrict__ p3d, const float* __restrict__ rm) {
    int n = blockIdx.x * blockDim.x + threadIdx.x;
    if (n >= NP) return;
    float X = p3d[3*n], Y = p3d[3*n+1], Z = p3d[3*n+2];
    float px = rm[0]*X + rm[1]*Y + rm[2]*Z + rm[3];
    float py = rm[4]*X + rm[5]*Y + rm[6]*Z + rm[7];
    float pz = rm[8]*X + rm[9]*Y + rm[10]*Z + rm[11];
    float pw = rm[12]*X + rm[13]*Y + rm[14]*Z + rm[15];
    d_pts3d0[3*n]   = px / pw;
    d_pts3d0[3*n+1] = py / pw;
    d_pts3d0[3*n+2] = pz / pw;
}

// ---------------- init: relative = q @ inv(r) ----------------
__global__ void k_init_state(const float* __restrict__ q, const float* __restrict__ r) {
    double M[4][8];
    for (int i = 0; i < 4; i++)
        for (int j = 0; j < 4; j++) { M[i][j] = r[i*4+j]; M[i][4+j] = (i == j) ? 1.0 : 0.0; }
    for (int col = 0; col < 4; col++) {
        int piv = col; double best = fabs(M[col][col]);
        for (int i = col+1; i < 4; i++) if (fabs(M[i][col]) > best) { best = fabs(M[i][col]); piv = i; }
        if (piv != col) for (int j = 0; j < 8; j++) { double tmp = M[col][j]; M[col][j] = M[piv][j]; M[piv][j] = tmp; }
        double inv = 1.0 / M[col][col];
        for (int j = 0; j < 8; j++) M[col][j] *= inv;
        for (int i = 0; i < 4; i++) if (i != col) {
            double f = M[i][col];
            for (int j = 0; j < 8; j++) M[i][j] -= f * M[col][j];
        }
    }
    for (int i = 0; i < 3; i++) {
        for (int j = 0; j < 4; j++) {
            double s = 0.0;
            for (int k = 0; k < 4; k++) s += (double)q[i*4+k] * M[k][4+j];
            if (j < 3) { d_R[i*3+j] = (float)s; d_Rc[i*3+j] = (float)s; }
            else       { d_t[i] = (float)s; d_tc[i] = (float)s; }
        }
    }
    d_lam = 0.01f;
    d_sel = 0;
    d_redo = 1;
}

// ---------------- projection helper ----------------
__device__ __forceinline__ void project_pt(int n, const float* R, const float* t,
                                           const float* __restrict__ Km,
                                           float& px, float& py, float& pz,
                                           float& p2x, float& p2y) {
    float X = d_pts3d0[3*n], Y = d_pts3d0[3*n+1], Z = d_pts3d0[3*n+2];
    px = R[0]*X + R[1]*Y + R[2]*Z + t[0];
    py = R[3]*X + R[4]*Y + R[5]*Z + t[1];
    pz = R[6]*X + R[7]*Y + R[8]*Z + t[2];
    float qx = Km[0]*px + Km[1]*py + Km[2]*pz;
    float qy = Km[3]*px + Km[4]*py + Km[5]*pz;
    float qz = Km[6]*px + Km[7]*py + Km[8]*pz;
    p2x = qx / qz; p2y = qy / qz;
}

__device__ __forceinline__ void unpack_g(uint4 q, float gx[4], float gy[4]) {
    float2 a = __bfloat1622float2(*reinterpret_cast<__nv_bfloat162*>(&q.x));
    float2 b = __bfloat1622float2(*reinterpret_cast<__nv_bfloat162*>(&q.y));
    float2 c = __bfloat1622float2(*reinterpret_cast<__nv_bfloat162*>(&q.z));
    float2 d = __bfloat1622float2(*reinterpret_cast<__nv_bfloat162*>(&q.w));
    gx[0] = a.x; gx[1] = a.y; gx[2] = b.x; gx[3] = b.y;
    gy[0] = c.x; gy[1] = c.y; gy[2] = d.x; gy[3] = d.y;
}

// ---------------- FUSED: candidate cost + Jacobian partials at candidate pose ----------------
__global__ void __launch_bounds__(256) k_cost_jac(const float* __restrict__ Km) {
    int n = blockIdx.x;
    int tid = threadIdx.x;
    int wbuf = d_sel ^ 1;          // candidate buffer
    float R[9], t[3];
#pragma unroll
    for (int i = 0; i < 9; i++) R[i] = d_Rc[i];
#pragma unroll
    for (int i = 0; i < 3; i++) t[i] = d_tc[i];
    float px, py, pz, p2x, p2y;
    project_pt(n, R, t, Km, px, py, pz, p2x, p2y);
    float ix = fminf(fmaxf(p2x * SRINV, 0.f), (float)(WW-1));
    float iy = fminf(fmaxf(p2y * SRINV, 0.f), (float)(HH-1));
    BilinSetup s = bilin_setup(ix, iy);

    const float4* I1 = reinterpret_cast<const float4*>(d_img1T);
    const uint4*  G  = reinterpret_cast<const uint4*>(d_gT);
    const float4* F0 = reinterpret_cast<const float4*>(d_feat0) + (size_t)n * C4;
    int c = tid;

    float4 i00 = I1[(size_t)s.b00*C4 + c], i10 = I1[(size_t)s.b10*C4 + c];
    float4 i01 = I1[(size_t)s.b01*C4 + c], i11 = I1[(size_t)s.b11*C4 + c];
    uint4 q00 = G[(size_t)s.b00*C4 + c];
    uint4 q10 = G[(size_t)s.b10*C4 + c];
    uint4 q01 = G[(size_t)s.b01*C4 + c];
    uint4 q11 = G[(size_t)s.b11*C4 + c];
    float4 f0 = F0[c];

    float gx00[4], gy00[4], gx10[4], gy10[4], gx01[4], gy01[4], gx11[4], gy11[4];
    unpack_g(q00, gx00, gy00);
    unpack_g(q10, gx10, gy10);
    unpack_g(q01, gx01, gy01);
    unpack_g(q11, gx11, gy11);
    float i0v[4] = { i00.x, i00.y, i00.z, i00.w };
    float i1v[4] = { i10.x, i10.y, i10.z, i10.w };
    float i2v[4] = { i01.x, i01.y, i01.z, i01.w };
    float i3v[4] = { i11.x, i11.y, i11.z, i11.w };
    float f0v[4] = { f0.x, f0.y, f0.z, f0.w };

    float cst = 0.f, sx = 0.f, sy = 0.f, sxx = 0.f, sxy = 0.f, syy = 0.f;
#pragma unroll
    for (int j = 0; j < 4; j++) {
        float f1 = bil(i0v[j], i1v[j], i2v[j], i3v[j], s);
        float e  = f1 - f0v[j];
        float jx = bil(gx00[j], gx10[j], gx01[j], gx11[j], s);
        float jy = bil(gy00[j], gy10[j], gy01[j], gy11[j], s);
        cst += e*e;
        sx += jx*e; sy += jy*e;
        sxx += jx*jx; sxy += jx*jy; syy += jy*jy;
    }

#pragma unroll
    for (int off = 16; off; off >>= 1) {
        cst += __shfl_down_sync(0xffffffffu, cst, off);
        sx  += __shfl_down_sync(0xffffffffu, sx,  off);
        sy  += __shfl_down_sync(0xffffffffu, sy,  off);
        sxx += __shfl_down_sync(0xffffffffu, sxx, off);
        sxy += __shfl_down_sync(0xffffffffu, sxy, off);
        syy += __shfl_down_sync(0xffffffffu, syy, off);
    }
    __shared__ float sm[8][6];
    int wid = tid >> 5, lane = tid & 31;
    if (lane == 0) {
        sm[wid][0] = cst; sm[wid][1] = sx; sm[wid][2] = sy;
        sm[wid][3] = sxx; sm[wid][4] = sxy; sm[wid][5] = syy;
    }
    __syncthreads();
    if (tid == 0) {
        float CS = 0.f, SX = 0.f, SY = 0.f, SXX = 0.f, SXY = 0.f, SYY = 0.f;
#pragma unroll
        for (int w = 0; w < 8; w++) {
            CS += sm[w][0]; SX += sm[w][1]; SY += sm[w][2];
            SXX += sm[w][3]; SXY += sm[w][4]; SYY += sm[w][5];
        }
        d_costpt[n] = CS;
        d_candp2[2*n]   = p2x;
        d_candp2[2*n+1] = p2y;

        float fx = Km[0], fy = Km[4];
        float invz = 1.f / pz;
        float sc = invz * SRINV;
        float a00 = fx * sc, a01 = 0.f, a02 = -fx * px * invz * sc;
        float a10 = 0.f, a11 = fy * sc, a12 = -fy * py * invz * sc;
        float A0[6], A1[6];
        A0[0] = a00; A0[1] = a01; A0[2] = a02;
        A1[0] = a10; A1[1] = a11; A1[2] = a12;
        A0[3] = -(a01*pz - a02*py);
        A0[4] = -(-a00*pz + a02*px);
        A0[5] = -(a00*py - a01*px);
        A1[3] = -(a11*pz - a12*py);
        A1[4] = -(-a10*pz + a12*px);
        A1[5] = -(a10*py - a11*px);

        float* P = d_part[wbuf];
#pragma unroll
        for (int k = 0; k < 6; k++)
            P[k*NP + n] = SX*A0[k] + SY*A1[k];
        int idx = 6;
#pragma unroll
        for (int k = 0; k < 6; k++)
#pragma unroll
            for (int l = k; l < 6; l++) {
                P[idx*NP + n] = SXX*A0[k]*A0[l] + SXY*(A0[k]*A1[l] + A1[k]*A0[l]) + SYY*A1[k]*A1[l];
                idx++;
            }
    }
}

// ---------------- fused: reduce g/H (if pose changed) + fp32 LM solve ----------------
__global__ void __launch_bounds__(256) k_reduce_solve() {
    int tid = threadIdx.x;
    if (d_redo != 0) {
        const float* P = d_part[d_sel];
        float acc[27];
#pragma unroll
        for (int k = 0; k < 27; k++) acc[k] = 0.f;
        for (int n = tid; n < NP; n += 256)
#pragma unroll
            for (int k = 0; k < 27; k++) acc[k] += P[k*NP + n];
        __shared__ float sm[27][256];
#pragma unroll
        for (int k = 0; k < 27; k++) sm[k][tid] = acc[k];
        __syncthreads();
        for (int sgap = 128; sgap; sgap >>= 1) {
            if (tid < sgap)
#pragma unroll
                for (int k = 0; k < 27; k++) sm[k][tid] += sm[k][tid + sgap];
            __syncthreads();
        }
        if (tid == 0) {
#pragma unroll
            for (int k = 0; k < 6; k++) d_gv[k] = sm[k][0];
            int idx = 6;
            for (int k = 0; k < 6; k++)
                for (int l = k; l < 6; l++) {
                    d_Hm[k*6+l] = sm[idx][0];
                    d_Hm[l*6+k] = sm[idx][0];
                    idx++;
                }
        }
        __syncthreads();
    }
    if (tid != 0) return;

    // ---- fp32 LM solve, single thread ----
    float Hd[6][7];
    float lam = d_lam;
    for (int k = 0; k < 6; k++) {
        for (int l = 0; l < 6; l++) Hd[k][l] = d_Hm[k*6+l];
        Hd[k][k] += (d_Hm[k*6+k] + 1e-9f) * lam;
        Hd[k][6] = -d_gv[k];
    }
    for (int col = 0; col < 6; col++) {
        int piv = col; float best = fabsf(Hd[col][col]);
        for (int r = col+1; r < 6; r++) if (fabsf(Hd[r][col]) > best) { best = fabsf(Hd[r][col]); piv = r; }
        if (piv != col) for (int j = 0; j < 7; j++) { float tmp = Hd[col][j]; Hd[col][j] = Hd[piv][j]; Hd[piv][j] = tmp; }
        float ip = 1.0f / Hd[col][col];
        for (int r = col+1; r < 6; r++) {
            float f = Hd[r][col] * ip;
            for (int j = col; j < 7; j++) Hd[r][j] -= f * Hd[col][j];
        }
    }
    float delta[6];
    for (int r = 5; r >= 0; r--) {
        float sv = Hd[r][6];
        for (int j = r+1; j < 6; j++) sv -= Hd[r][j] * delta[j];
        delta[r] = sv / Hd[r][r];
    }
    float w0 = delta[3], w1 = delta[4], w2 = delta[5];
    float th2 = w0*w0 + w1*w1 + w2*w2;
    float th = sqrtf(fmaxf(th2, 1e-24f));
    float Ac = (th2 < 1e-16f) ? 1.0f : sinf(th) / th;
    float Bc = (th2 < 1e-16f) ? 0.5f : (1.0f - cosf(th)) / fmaxf(th2, 1e-24f);
    float dr[3][3];
    dr[0][0] = 1.0f + Bc*(w0*w0 - th2);
    dr[0][1] = -Ac*w2 + Bc*w0*w1;
    dr[0][2] =  Ac*w1 + Bc*w0*w2;
    dr[1][0] =  Ac*w2 + Bc*w1*w0;
    dr[1][1] = 1.0f + Bc*(w1*w1 - th2);
    dr[1][2] = -Ac*w0 + Bc*w1*w2;
    dr[2][0] = -Ac*w1 + Bc*w2*w0;
    dr[2][1] =  Ac*w0 + Bc*w2*w1;
    dr[2][2] = 1.0f + Bc*(w2*w2 - th2);
    for (int i = 0; i < 3; i++) {
        for (int j = 0; j < 3; j++) {
            float sv = 0.0f;
            for (int k = 0; k < 3; k++) sv += dr[i][k] * d_R[k*3+j];
            d_Rc[i*3+j] = sv;
        }
        float sv = delta[i];
        for (int k = 0; k < 3; k++) sv += dr[i][k] * d_t[k];
        d_tc[i] = sv;
    }
}

// ---------------- fused: accept/reject + best copy ----------------
__global__ void __launch_bounds__(256) k_accept_copy(int mode, float* __restrict__ out) {
    int tid = threadIdx.x;
    float acc = 0.f;
    for (int n = tid; n < NP; n += 256) acc += d_costpt[n];
    __shared__ float sm[256];
    __shared__ int s_acc;
    sm[tid] = acc;
    __syncthreads();
    for (int sgap = 128; sgap; sgap >>= 1) {
        if (tid < sgap) sm[tid] += sm[tid + sgap];
        __syncthreads();
    }
    if (tid == 0) {
        float newc = sm[0] / (float)NP;
        if (mode == 0) {
            d_prev = newc;
            d_sel = 1;     // initial partials live in buf 1
            d_redo = 1;
            s_acc = 1;
        } else {
            bool a = (newc <= d_prev);
            if (a) {
#pragma unroll
                for (int i = 0; i < 9; i++) d_R[i] = d_Rc[i];
#pragma unroll
                for (int i = 0; i < 3; i++) d_t[i] = d_tc[i];
                d_prev = newc;
                d_sel ^= 1;
            }
            d_redo = a ? 1 : 0;
            float l = d_lam * (a ? 0.1f : 10.f);
            d_lam = fminf(fmaxf(l, 1e-6f), 100.f);
            s_acc = a ? 1 : 0;
        }
    }
    __syncthreads();
    if (s_acc) {
        const float2* src = reinterpret_cast<const float2*>(d_candp2);
        float2* dst = reinterpret_cast<float2*>(out);
        for (int n = tid; n < NP; n += 256) dst[n] = src[n];
    }
}

// ---------------- launch ----------------
extern "C" void kernel_launch(void* const* d_in, const int* in_sizes, int n_in,
                              void* d_out, int out_size) {
    const float* imgf0 = (const float*)d_in[0];
    const float* imgf1 = (const float*)d_in[1];
    const float* pts2d = (const float*)d_in[2];
    const float* pts3d = (const float*)d_in[3];
    const float* qm    = (const float*)d_in[4];
    const float* rm    = (const float*)d_in[5];
    const float* Km    = (const float*)d_in[6];
    float* out = (float*)d_out;

    dim3 tb(32, 8);
    k_transpose<<<dim3(HW/32, CC/32), tb>>>(imgf0, 0);
    k_transpose<<<dim3(HW/32, CC/32), tb>>>(imgf1, 1);
    k_sobel<<<dim3(WW, HH), 256>>>();
    k_feat0<<<NP, 256>>>(pts2d);
    k_pts3d0<<<NP/256, 256>>>(pts3d, rm);
    k_init_state<<<1, 1>>>(qm, rm);

    // initial: candidate == init pose; computes cost + partials(init)
    k_cost_jac<<<NP, 256>>>(Km);
    k_accept_copy<<<1, 256>>>(0, out);

    for (int it = 0; it < NITERS; it++) {
        k_reduce_solve<<<1, 256>>>();
        k_cost_jac<<<NP, 256>>>(Km);
        k_accept_copy<<<1, 256>>>(1, out);
    }
}

// round 5
// speedup vs baseline: 1.8193x; 1.0625x over previous
#include <cuda_runtime.h>
#include <cuda_bf16.h>
#include <math.h>

#define CC 1024
#define C4 (CC/4)
#define HH 128
#define WW 128
#define HW (HH*WW)
#define NP 4096
#define SRINV 0.125f
#define NITERS 10

// ---------------- device state ----------------
__device__ __nv_bfloat16 d_img0B[HW*CC];     // imgf0 [H,W,C] bf16
__device__ __nv_bfloat16 d_img1B[HW*CC];     // imgf1 [H,W,C] bf16
__device__ __nv_bfloat16 d_gT[HW*CC*2];      // packed bf16 per pix/c4: {gx0..3, gy0..3}
__device__ __nv_bfloat16 d_feat0B[NP*CC];    // reference features bf16
__device__ float d_pts3d0[NP*3];
__device__ float d_part[2][27*NP];           // per-point partials, double-buffered
__device__ float d_costpt[NP];
__device__ float d_candp2[NP*2];
__device__ float d_R[9];
__device__ float d_t[3];
__device__ float d_Rc[9];
__device__ float d_tc[3];
__device__ float d_lam;
__device__ float d_prev;
__device__ int   d_sel;    // which partial buffer is the accepted one
__device__ float d_Hm[36];
__device__ float d_gv[6];

// ---------------- prep: CHW fp32 -> HWC bf16 transpose ----------------
__global__ void k_transpose(const float* __restrict__ src, int dst_sel) {
    __nv_bfloat16* dst = dst_sel ? d_img1B : d_img0B;
    __shared__ float tile[32][33];
    int hw0 = blockIdx.x * 32;
    int c0  = blockIdx.y * 32;
#pragma unroll
    for (int i = threadIdx.y; i < 32; i += 8)
        tile[i][threadIdx.x] = src[(size_t)(c0 + i) * HW + hw0 + threadIdx.x];
    __syncthreads();
#pragma unroll
    for (int i = threadIdx.y; i < 32; i += 8)
        dst[(size_t)(hw0 + i) * CC + c0 + threadIdx.x] = __float2bfloat16(tile[threadIdx.x][i]);
}

// helpers: bf16x4 load/unpack
__device__ __forceinline__ void unpack_b4(uint2 q, float f[4]) {
    float2 a = __bfloat1622float2(*reinterpret_cast<__nv_bfloat162*>(&q.x));
    float2 b = __bfloat1622float2(*reinterpret_cast<__nv_bfloat162*>(&q.y));
    f[0] = a.x; f[1] = a.y; f[2] = b.x; f[3] = b.y;
}
__device__ __forceinline__ uint2 pack_b4(const float f[4]) {
    __nv_bfloat162 a = __floats2bfloat162_rn(f[0], f[1]);
    __nv_bfloat162 b = __floats2bfloat162_rn(f[2], f[3]);
    uint2 q;
    q.x = *reinterpret_cast<unsigned*>(&a);
    q.y = *reinterpret_cast<unsigned*>(&b);
    return q;
}

// ---------------- prep: sobel on bf16 HWC img1, packed bf16 grads out ----------------
__global__ void __launch_bounds__(256) k_sobel() {
    int x = blockIdx.x, y = blockIdx.y;
    int c = threadIdx.x;
    const uint2* img = reinterpret_cast<const uint2*>(d_img1B);
    float v[3][3][4];
#pragma unroll
    for (int dy = -1; dy <= 1; dy++) {
#pragma unroll
        for (int dx = -1; dx <= 1; dx++) {
            int yy = y + dy, xx = x + dx;
            float f[4] = {0.f, 0.f, 0.f, 0.f};
            if (yy >= 0 && yy < HH && xx >= 0 && xx < WW) {
                uint2 q = img[(size_t)(yy * WW + xx) * C4 + c];
                unpack_b4(q, f);
            }
#pragma unroll
            for (int j = 0; j < 4; j++) v[dy+1][dx+1][j] = f[j];
        }
    }
    float gx[4], gy[4];
#pragma unroll
    for (int j = 0; j < 4; j++) {
        gx[j] = (v[0][2][j] - v[0][0][j] + 2.f*(v[1][2][j] - v[1][0][j]) + v[2][2][j] - v[2][0][j]) * 0.125f;
        gy[j] = (v[2][0][j] - v[0][0][j] + 2.f*(v[2][1][j] - v[0][1][j]) + v[2][2][j] - v[0][2][j]) * 0.125f;
    }
    uint2 px = pack_b4(gx), py = pack_b4(gy);
    uint4 o;
    o.x = px.x; o.y = px.y; o.z = py.x; o.w = py.y;
    reinterpret_cast<uint4*>(d_gT)[(size_t)(y * WW + x) * C4 + c] = o;
}

// ---------------- bilinear setup ----------------
struct BilinSetup {
    int b00, b10, b01, b11;
    float w00, w10, w01, w11;
};
__device__ __forceinline__ BilinSetup bilin_setup(float x, float y) {
    BilinSetup s;
    float x0f = floorf(x), y0f = floorf(y);
    float wx = x - x0f, wy = y - y0f;
    int x0 = min(max((int)x0f, 0), WW-1);
    int x1 = min(max(x0 + 1, 0), WW-1);
    int y0 = min(max((int)y0f, 0), HH-1);
    int y1 = min(max(y0 + 1, 0), HH-1);
    s.w00 = (1.f-wx)*(1.f-wy); s.w10 = wx*(1.f-wy);
    s.w01 = (1.f-wx)*wy;       s.w11 = wx*wy;
    s.b00 = (y0*WW + x0); s.b10 = (y0*WW + x1);
    s.b01 = (y1*WW + x0); s.b11 = (y1*WW + x1);
    return s;
}
__device__ __forceinline__ float bil(float a, float b, float c, float d, const BilinSetup& s) {
    return a*s.w00 + b*s.w10 + c*s.w01 + d*s.w11;
}

// ---------------- prep: feat0 (gather from bf16 img0, store bf16) ----------------
__global__ void __launch_bounds__(256) k_feat0(const float* __restrict__ pts2d) {
    int n = blockIdx.x;
    BilinSetup s = bilin_setup(pts2d[2*n] * SRINV, pts2d[2*n+1] * SRINV);
    const uint2* img = reinterpret_cast<const uint2*>(d_img0B);
    int c = threadIdx.x;
    float f00[4], f10[4], f01[4], f11[4], o[4];
    unpack_b4(img[(size_t)s.b00*C4 + c], f00);
    unpack_b4(img[(size_t)s.b10*C4 + c], f10);
    unpack_b4(img[(size_t)s.b01*C4 + c], f01);
    unpack_b4(img[(size_t)s.b11*C4 + c], f11);
#pragma unroll
    for (int j = 0; j < 4; j++)
        o[j] = bil(f00[j], f10[j], f01[j], f11[j], s);
    reinterpret_cast<uint2*>(d_feat0B)[(size_t)n * C4 + c] = pack_b4(o);
}

// ---------------- prep: pts3d0 ----------------
__global__ void k_pts3d0(const float* __restrict__ p3d, const float* __restrict__ rm) {
    int n = blockIdx.x * blockDim.x + threadIdx.x;
    if (n >= NP) return;
    float X = p3d[3*n], Y = p3d[3*n+1], Z = p3d[3*n+2];
    float px = rm[0]*X + rm[1]*Y + rm[2]*Z + rm[3];
    float py = rm[4]*X + rm[5]*Y + rm[6]*Z + rm[7];
    float pz = rm[8]*X + rm[9]*Y + rm[10]*Z + rm[11];
    float pw = rm[12]*X + rm[13]*Y + rm[14]*Z + rm[15];
    d_pts3d0[3*n]   = px / pw;
    d_pts3d0[3*n+1] = py / pw;
    d_pts3d0[3*n+2] = pz / pw;
}

// ---------------- init: relative = q @ inv(r) ----------------
__global__ void k_init_state(const float* __restrict__ q, const float* __restrict__ r) {
    double M[4][8];
    for (int i = 0; i < 4; i++)
        for (int j = 0; j < 4; j++) { M[i][j] = r[i*4+j]; M[i][4+j] = (i == j) ? 1.0 : 0.0; }
    for (int col = 0; col < 4; col++) {
        int piv = col; double best = fabs(M[col][col]);
        for (int i = col+1; i < 4; i++) if (fabs(M[i][col]) > best) { best = fabs(M[i][col]); piv = i; }
        if (piv != col) for (int j = 0; j < 8; j++) { double tmp = M[col][j]; M[col][j] = M[piv][j]; M[piv][j] = tmp; }
        double inv = 1.0 / M[col][col];
        for (int j = 0; j < 8; j++) M[col][j] *= inv;
        for (int i = 0; i < 4; i++) if (i != col) {
            double f = M[i][col];
            for (int j = 0; j < 8; j++) M[i][j] -= f * M[col][j];
        }
    }
    for (int i = 0; i < 3; i++) {
        for (int j = 0; j < 4; j++) {
            double s = 0.0;
            for (int k = 0; k < 4; k++) s += (double)q[i*4+k] * M[k][4+j];
            if (j < 3) { d_R[i*3+j] = (float)s; d_Rc[i*3+j] = (float)s; }
            else       { d_t[i] = (float)s; d_tc[i] = (float)s; }
        }
    }
    d_lam = 0.01f;
    d_sel = 0;
}

// ---------------- projection helper ----------------
__device__ __forceinline__ void project_pt(int n, const float* R, const float* t,
                                           const float* __restrict__ Km,
                                           float& px, float& py, float& pz,
                                           float& p2x, float& p2y) {
    float X = d_pts3d0[3*n], Y = d_pts3d0[3*n+1], Z = d_pts3d0[3*n+2];
    px = R[0]*X + R[1]*Y + R[2]*Z + t[0];
    py = R[3]*X + R[4]*Y + R[5]*Z + t[1];
    pz = R[6]*X + R[7]*Y + R[8]*Z + t[2];
    float qx = Km[0]*px + Km[1]*py + Km[2]*pz;
    float qy = Km[3]*px + Km[4]*py + Km[5]*pz;
    float qz = Km[6]*px + Km[7]*py + Km[8]*pz;
    p2x = qx / qz; p2y = qy / qz;
}

__device__ __forceinline__ void unpack_g(uint4 q, float gx[4], float gy[4]) {
    float2 a = __bfloat1622float2(*reinterpret_cast<__nv_bfloat162*>(&q.x));
    float2 b = __bfloat1622float2(*reinterpret_cast<__nv_bfloat162*>(&q.y));
    float2 c = __bfloat1622float2(*reinterpret_cast<__nv_bfloat162*>(&q.z));
    float2 d = __bfloat1622float2(*reinterpret_cast<__nv_bfloat162*>(&q.w));
    gx[0] = a.x; gx[1] = a.y; gx[2] = b.x; gx[3] = b.y;
    gy[0] = c.x; gy[1] = c.y; gy[2] = d.x; gy[3] = d.y;
}

// ---------------- FUSED: candidate cost + Jacobian partials at candidate pose ----------------
__global__ void __launch_bounds__(256) k_cost_jac(const float* __restrict__ Km) {
    int n = blockIdx.x;
    int tid = threadIdx.x;
    int wbuf = d_sel ^ 1;          // candidate buffer
    float R[9], t[3];
#pragma unroll
    for (int i = 0; i < 9; i++) R[i] = d_Rc[i];
#pragma unroll
    for (int i = 0; i < 3; i++) t[i] = d_tc[i];
    float px, py, pz, p2x, p2y;
    project_pt(n, R, t, Km, px, py, pz, p2x, p2y);
    float ix = fminf(fmaxf(p2x * SRINV, 0.f), (float)(WW-1));
    float iy = fminf(fmaxf(p2y * SRINV, 0.f), (float)(HH-1));
    BilinSetup s = bilin_setup(ix, iy);

    const uint2* I1 = reinterpret_cast<const uint2*>(d_img1B);
    const uint4* G  = reinterpret_cast<const uint4*>(d_gT);
    const uint2* F0 = reinterpret_cast<const uint2*>(d_feat0B) + (size_t)n * C4;
    int c = tid;

    uint2 bi00 = I1[(size_t)s.b00*C4 + c], bi10 = I1[(size_t)s.b10*C4 + c];
    uint2 bi01 = I1[(size_t)s.b01*C4 + c], bi11 = I1[(size_t)s.b11*C4 + c];
    uint4 q00 = G[(size_t)s.b00*C4 + c];
    uint4 q10 = G[(size_t)s.b10*C4 + c];
    uint4 q01 = G[(size_t)s.b01*C4 + c];
    uint4 q11 = G[(size_t)s.b11*C4 + c];
    uint2 bf0 = F0[c];

    float i0v[4], i1v[4], i2v[4], i3v[4], f0v[4];
    unpack_b4(bi00, i0v); unpack_b4(bi10, i1v);
    unpack_b4(bi01, i2v); unpack_b4(bi11, i3v);
    unpack_b4(bf0, f0v);
    float gx00[4], gy00[4], gx10[4], gy10[4], gx01[4], gy01[4], gx11[4], gy11[4];
    unpack_g(q00, gx00, gy00);
    unpack_g(q10, gx10, gy10);
    unpack_g(q01, gx01, gy01);
    unpack_g(q11, gx11, gy11);

    float cst = 0.f, sx = 0.f, sy = 0.f, sxx = 0.f, sxy = 0.f, syy = 0.f;
#pragma unroll
    for (int j = 0; j < 4; j++) {
        float f1 = bil(i0v[j], i1v[j], i2v[j], i3v[j], s);
        float e  = f1 - f0v[j];
        float jx = bil(gx00[j], gx10[j], gx01[j], gx11[j], s);
        float jy = bil(gy00[j], gy10[j], gy01[j], gy11[j], s);
        cst += e*e;
        sx += jx*e; sy += jy*e;
        sxx += jx*jx; sxy += jx*jy; syy += jy*jy;
    }

#pragma unroll
    for (int off = 16; off; off >>= 1) {
        cst += __shfl_down_sync(0xffffffffu, cst, off);
        sx  += __shfl_down_sync(0xffffffffu, sx,  off);
        sy  += __shfl_down_sync(0xffffffffu, sy,  off);
        sxx += __shfl_down_sync(0xffffffffu, sxx, off);
        sxy += __shfl_down_sync(0xffffffffu, sxy, off);
        syy += __shfl_down_sync(0xffffffffu, syy, off);
    }
    __shared__ float sm[8][6];
    int wid = tid >> 5, lane = tid & 31;
    if (lane == 0) {
        sm[wid][0] = cst; sm[wid][1] = sx; sm[wid][2] = sy;
        sm[wid][3] = sxx; sm[wid][4] = sxy; sm[wid][5] = syy;
    }
    __syncthreads();
    if (tid == 0) {
        float CS = 0.f, SX = 0.f, SY = 0.f, SXX = 0.f, SXY = 0.f, SYY = 0.f;
#pragma unroll
        for (int w = 0; w < 8; w++) {
            CS += sm[w][0]; SX += sm[w][1]; SY += sm[w][2];
            SXX += sm[w][3]; SXY += sm[w][4]; SYY += sm[w][5];
        }
        d_costpt[n] = CS;
        d_candp2[2*n]   = p2x;
        d_candp2[2*n+1] = p2y;

        float fx = Km[0], fy = Km[4];
        float invz = 1.f / pz;
        float sc = invz * SRINV;
        float a00 = fx * sc, a01 = 0.f, a02 = -fx * px * invz * sc;
        float a10 = 0.f, a11 = fy * sc, a12 = -fy * py * invz * sc;
        float A0[6], A1[6];
        A0[0] = a00; A0[1] = a01; A0[2] = a02;
        A1[0] = a10; A1[1] = a11; A1[2] = a12;
        A0[3] = -(a01*pz - a02*py);
        A0[4] = -(-a00*pz + a02*px);
        A0[5] = -(a00*py - a01*px);
        A1[3] = -(a11*pz - a12*py);
        A1[4] = -(-a10*pz + a12*px);
        A1[5] = -(a10*py - a11*px);

        float* P = d_part[wbuf];
#pragma unroll
        for (int k = 0; k < 6; k++)
            P[k*NP + n] = SX*A0[k] + SY*A1[k];
        int idx = 6;
#pragma unroll
        for (int k = 0; k < 6; k++)
#pragma unroll
            for (int l = k; l < 6; l++) {
                P[idx*NP + n] = SXX*A0[k]*A0[l] + SXY*(A0[k]*A1[l] + A1[k]*A0[l]) + SYY*A1[k]*A1[l];
                idx++;
            }
    }
}

// ---------------- FUSED: accept/reject + copy + reduce g/H + LM solve ----------------
__global__ void __launch_bounds__(256) k_update(int mode, float* __restrict__ out) {
    int tid = threadIdx.x;
    __shared__ float smc[256];
    __shared__ int s_acc, s_sel, s_redo;

    // ---- accept ----
    float acc = 0.f;
    for (int n = tid; n < NP; n += 256) acc += d_costpt[n];
    smc[tid] = acc;
    __syncthreads();
    for (int sgap = 128; sgap; sgap >>= 1) {
        if (tid < sgap) smc[tid] += smc[tid + sgap];
        __syncthreads();
    }
    if (tid == 0) {
        float newc = smc[0] / (float)NP;
        if (mode == 0) {
            d_prev = newc;
            d_sel = 1;
            s_sel = 1; s_redo = 1; s_acc = 1;
        } else {
            bool a = (newc <= d_prev);
            if (a) {
#pragma unroll
                for (int i = 0; i < 9; i++) d_R[i] = d_Rc[i];
#pragma unroll
                for (int i = 0; i < 3; i++) d_t[i] = d_tc[i];
                d_prev = newc;
                d_sel ^= 1;
            }
            float l = d_lam * (a ? 0.1f : 10.f);
            d_lam = fminf(fmaxf(l, 1e-6f), 100.f);
            s_acc = a ? 1 : 0;
            s_sel = d_sel;
            s_redo = a ? 1 : 0;
        }
    }
    __syncthreads();
    if (s_acc) {
        const float2* src = reinterpret_cast<const float2*>(d_candp2);
        float2* dst = reinterpret_cast<float2*>(out);
        for (int n = tid; n < NP; n += 256) dst[n] = src[n];
    }

    // ---- reduce partials (only if accepted pose changed) ----
    if (s_redo) {
        const float* P = d_part[s_sel];
        float a27[27];
#pragma unroll
        for (int k = 0; k < 27; k++) a27[k] = 0.f;
        for (int n = tid; n < NP; n += 256)
#pragma unroll
            for (int k = 0; k < 27; k++) a27[k] += P[k*NP + n];
        __shared__ float sm27[27][256];
#pragma unroll
        for (int k = 0; k < 27; k++) sm27[k][tid] = a27[k];
        __syncthreads();
        for (int sgap = 128; sgap; sgap >>= 1) {
            if (tid < sgap)
#pragma unroll
                for (int k = 0; k < 27; k++) sm27[k][tid] += sm27[k][tid + sgap];
            __syncthreads();
        }
        if (tid == 0) {
#pragma unroll
            for (int k = 0; k < 6; k++) d_gv[k] = sm27[k][0];
            int idx = 6;
            for (int k = 0; k < 6; k++)
                for (int l = k; l < 6; l++) {
                    d_Hm[k*6+l] = sm27[idx][0];
                    d_Hm[l*6+k] = sm27[idx][0];
                    idx++;
                }
        }
        __syncthreads();
    }
    if (tid != 0) return;

    // ---- fp32 LM solve, single thread ----
    float Hd[6][7];
    float lam = d_lam;
    for (int k = 0; k < 6; k++) {
        for (int l = 0; l < 6; l++) Hd[k][l] = d_Hm[k*6+l];
        Hd[k][k] += (d_Hm[k*6+k] + 1e-9f) * lam;
        Hd[k][6] = -d_gv[k];
    }
    for (int col = 0; col < 6; col++) {
        int piv = col; float best = fabsf(Hd[col][col]);
        for (int r = col+1; r < 6; r++) if (fabsf(Hd[r][col]) > best) { best = fabsf(Hd[r][col]); piv = r; }
        if (piv != col) for (int j = 0; j < 7; j++) { float tmp = Hd[col][j]; Hd[col][j] = Hd[piv][j]; Hd[piv][j] = tmp; }
        float ip = 1.0f / Hd[col][col];
        for (int r = col+1; r < 6; r++) {
            float f = Hd[r][col] * ip;
            for (int j = col; j < 7; j++) Hd[r][j] -= f * Hd[col][j];
        }
    }
    float delta[6];
    for (int r = 5; r >= 0; r--) {
        float sv = Hd[r][6];
        for (int j = r+1; j < 6; j++) sv -= Hd[r][j] * delta[j];
        delta[r] = sv / Hd[r][r];
    }
    float w0 = delta[3], w1 = delta[4], w2 = delta[5];
    float th2 = w0*w0 + w1*w1 + w2*w2;
    float th = sqrtf(fmaxf(th2, 1e-24f));
    float Ac = (th2 < 1e-16f) ? 1.0f : sinf(th) / th;
    float Bc = (th2 < 1e-16f) ? 0.5f : (1.0f - cosf(th)) / fmaxf(th2, 1e-24f);
    float dr[3][3];
    dr[0][0] = 1.0f + Bc*(w0*w0 - th2);
    dr[0][1] = -Ac*w2 + Bc*w0*w1;
    dr[0][2] =  Ac*w1 + Bc*w0*w2;
    dr[1][0] =  Ac*w2 + Bc*w1*w0;
    dr[1][1] = 1.0f + Bc*(w1*w1 - th2);
    dr[1][2] = -Ac*w0 + Bc*w1*w2;
    dr[2][0] = -Ac*w1 + Bc*w2*w0;
    dr[2][1] =  Ac*w0 + Bc*w2*w1;
    dr[2][2] = 1.0f + Bc*(w2*w2 - th2);
    for (int i = 0; i < 3; i++) {
        for (int j = 0; j < 3; j++) {
            float sv = 0.0f;
            for (int k = 0; k < 3; k++) sv += dr[i][k] * d_R[k*3+j];
            d_Rc[i*3+j] = sv;
        }
        float sv = delta[i];
        for (int k = 0; k < 3; k++) sv += dr[i][k] * d_t[k];
        d_tc[i] = sv;
    }
}

// ---------------- launch ----------------
extern "C" void kernel_launch(void* const* d_in, const int* in_sizes, int n_in,
                              void* d_out, int out_size) {
    const float* imgf0 = (const float*)d_in[0];
    const float* imgf1 = (const float*)d_in[1];
    const float* pts2d = (const float*)d_in[2];
    const float* pts3d = (const float*)d_in[3];
    const float* qm    = (const float*)d_in[4];
    const float* rm    = (const float*)d_in[5];
    const float* Km    = (const float*)d_in[6];
    float* out = (float*)d_out;

    dim3 tb(32, 8);
    k_transpose<<<dim3(HW/32, CC/32), tb>>>(imgf0, 0);
    k_transpose<<<dim3(HW/32, CC/32), tb>>>(imgf1, 1);
    k_sobel<<<dim3(WW, HH), 256>>>();
    k_feat0<<<NP, 256>>>(pts2d);
    k_pts3d0<<<NP/256, 256>>>(pts3d, rm);
    k_init_state<<<1, 1>>>(qm, rm);

    // initial: candidate == init pose; computes cost + partials(init)
    k_cost_jac<<<NP, 256>>>(Km);
    k_update<<<1, 256>>>(0, out);   // sets prev, reduces init partials, solves -> candidate 1

    for (int it = 0; it < NITERS; it++) {
        k_cost_jac<<<NP, 256>>>(Km);
        k_update<<<1, 256>>>(1, out);  // accept?, reduce, solve -> next candidate
    }
}

// round 6
// speedup vs baseline: 1.9866x; 1.0919x over previous
#include <cuda_runtime.h>
#include <cuda_bf16.h>
#include <cuda_fp8.h>
#include <math.h>

#define CC 1024
#define C4 (CC/4)
#define HH 128
#define WW 128
#define HW (HH*WW)
#define NP 4096
#define SRINV 0.125f
#define NITERS 10
#define GSCALE 16.0f
#define GSCALE_INV (1.0f/16.0f)

// ---------------- device state ----------------
__device__ __nv_bfloat16 d_img0B[HW*CC];     // imgf0 [H,W,C] bf16
__device__ __nv_bfloat16 d_img1B[HW*CC];     // imgf1 [H,W,C] bf16
__device__ uint2 d_g8[HW*C4];                // fp8 e4m3 grads: per pix/c4 {gx0..3}{gy0..3}, pre-scaled by 16
__device__ __nv_bfloat16 d_feat0B[NP*CC];    // reference features bf16
__device__ float d_pts3d0[NP*3];
__device__ float d_part[2][8*NP];            // per-point: SX,SY,SXX,SXY,SYY,px,py,pz (double-buffered)
__device__ float d_costpt[NP];
__device__ float d_candp2[NP*2];
__device__ float d_R[9];
__device__ float d_t[3];
__device__ float d_Rc[9];
__device__ float d_tc[3];
__device__ float d_lam;
__device__ float d_prev;
__device__ int   d_sel;
__device__ float d_Hm[36];
__device__ float d_gv[6];

// ---------------- prep: CHW fp32 -> HWC bf16 transpose ----------------
__global__ void k_transpose(const float* __restrict__ src, int dst_sel) {
    __nv_bfloat16* dst = dst_sel ? d_img1B : d_img0B;
    __shared__ float tile[32][33];
    int hw0 = blockIdx.x * 32;
    int c0  = blockIdx.y * 32;
#pragma unroll
    for (int i = threadIdx.y; i < 32; i += 8)
        tile[i][threadIdx.x] = src[(size_t)(c0 + i) * HW + hw0 + threadIdx.x];
    __syncthreads();
#pragma unroll
    for (int i = threadIdx.y; i < 32; i += 8)
        dst[(size_t)(hw0 + i) * CC + c0 + threadIdx.x] = __float2bfloat16(tile[threadIdx.x][i]);
}

// helpers: bf16x4 load/unpack
__device__ __forceinline__ void unpack_b4(uint2 q, float f[4]) {
    float2 a = __bfloat1622float2(*reinterpret_cast<__nv_bfloat162*>(&q.x));
    float2 b = __bfloat1622float2(*reinterpret_cast<__nv_bfloat162*>(&q.y));
    f[0] = a.x; f[1] = a.y; f[2] = b.x; f[3] = b.y;
}
__device__ __forceinline__ uint2 pack_b4(const float f[4]) {
    __nv_bfloat162 a = __floats2bfloat162_rn(f[0], f[1]);
    __nv_bfloat162 b = __floats2bfloat162_rn(f[2], f[3]);
    uint2 q;
    q.x = *reinterpret_cast<unsigned*>(&a);
    q.y = *reinterpret_cast<unsigned*>(&b);
    return q;
}

// fp8 pack/unpack (4 values <-> 32 bits)
__device__ __forceinline__ unsigned pack_f8x4(const float f[4]) {
    __nv_fp8x2_storage_t lo = __nv_cvt_float2_to_fp8x2(make_float2(f[0], f[1]), __NV_SATFINITE, __NV_E4M3);
    __nv_fp8x2_storage_t hi = __nv_cvt_float2_to_fp8x2(make_float2(f[2], f[3]), __NV_SATFINITE, __NV_E4M3);
    return (unsigned)lo | ((unsigned)hi << 16);
}
__device__ __forceinline__ void unpack_f8x4(unsigned q, float f[4]) {
    __half2_raw h01 = __nv_cvt_fp8x2_to_halfraw2((__nv_fp8x2_storage_t)(q & 0xFFFF), __NV_E4M3);
    __half2_raw h23 = __nv_cvt_fp8x2_to_halfraw2((__nv_fp8x2_storage_t)(q >> 16),    __NV_E4M3);
    float2 a = __half22float2(*reinterpret_cast<__half2*>(&h01));
    float2 b = __half22float2(*reinterpret_cast<__half2*>(&h23));
    f[0] = a.x; f[1] = a.y; f[2] = b.x; f[3] = b.y;
}

// ---------------- prep: sobel on bf16 HWC img1, fp8 packed grads out ----------------
__global__ void __launch_bounds__(256) k_sobel() {
    int x = blockIdx.x, y = blockIdx.y;
    int c = threadIdx.x;
    const uint2* img = reinterpret_cast<const uint2*>(d_img1B);
    float v[3][3][4];
#pragma unroll
    for (int dy = -1; dy <= 1; dy++) {
#pragma unroll
        for (int dx = -1; dx <= 1; dx++) {
            int yy = y + dy, xx = x + dx;
            float f[4] = {0.f, 0.f, 0.f, 0.f};
            if (yy >= 0 && yy < HH && xx >= 0 && xx < WW) {
                uint2 q = img[(size_t)(yy * WW + xx) * C4 + c];
                unpack_b4(q, f);
            }
#pragma unroll
            for (int j = 0; j < 4; j++) v[dy+1][dx+1][j] = f[j];
        }
    }
    float gx[4], gy[4];
#pragma unroll
    for (int j = 0; j < 4; j++) {
        gx[j] = (v[0][2][j] - v[0][0][j] + 2.f*(v[1][2][j] - v[1][0][j]) + v[2][2][j] - v[2][0][j]) * (0.125f * GSCALE);
        gy[j] = (v[2][0][j] - v[0][0][j] + 2.f*(v[2][1][j] - v[0][1][j]) + v[2][2][j] - v[0][2][j]) * (0.125f * GSCALE);
    }
    uint2 o;
    o.x = pack_f8x4(gx);
    o.y = pack_f8x4(gy);
    d_g8[(size_t)(y * WW + x) * C4 + c] = o;
}

// ---------------- bilinear setup ----------------
struct BilinSetup {
    int b00, b10, b01, b11;
    float w00, w10, w01, w11;
};
__device__ __forceinline__ BilinSetup bilin_setup(float x, float y) {
    BilinSetup s;
    float x0f = floorf(x), y0f = floorf(y);
    float wx = x - x0f, wy = y - y0f;
    int x0 = min(max((int)x0f, 0), WW-1);
    int x1 = min(max(x0 + 1, 0), WW-1);
    int y0 = min(max((int)y0f, 0), HH-1);
    int y1 = min(max(y0 + 1, 0), HH-1);
    s.w00 = (1.f-wx)*(1.f-wy); s.w10 = wx*(1.f-wy);
    s.w01 = (1.f-wx)*wy;       s.w11 = wx*wy;
    s.b00 = (y0*WW + x0); s.b10 = (y0*WW + x1);
    s.b01 = (y1*WW + x0); s.b11 = (y1*WW + x1);
    return s;
}
__device__ __forceinline__ float bil(float a, float b, float c, float d, const BilinSetup& s) {
    return a*s.w00 + b*s.w10 + c*s.w01 + d*s.w11;
}

// ---------------- prep: feat0 ----------------
__global__ void __launch_bounds__(256) k_feat0(const float* __restrict__ pts2d) {
    int n = blockIdx.x;
    BilinSetup s = bilin_setup(pts2d[2*n] * SRINV, pts2d[2*n+1] * SRINV);
    const uint2* img = reinterpret_cast<const uint2*>(d_img0B);
    int c = threadIdx.x;
    float f00[4], f10[4], f01[4], f11[4], o[4];
    unpack_b4(img[(size_t)s.b00*C4 + c], f00);
    unpack_b4(img[(size_t)s.b10*C4 + c], f10);
    unpack_b4(img[(size_t)s.b01*C4 + c], f01);
    unpack_b4(img[(size_t)s.b11*C4 + c], f11);
#pragma unroll
    for (int j = 0; j < 4; j++)
        o[j] = bil(f00[j], f10[j], f01[j], f11[j], s);
    reinterpret_cast<uint2*>(d_feat0B)[(size_t)n * C4 + c] = pack_b4(o);
}

// ---------------- prep: pts3d0 ----------------
__global__ void k_pts3d0(const float* __restrict__ p3d, const float* __restrict__ rm) {
    int n = blockIdx.x * blockDim.x + threadIdx.x;
    if (n >= NP) return;
    float X = p3d[3*n], Y = p3d[3*n+1], Z = p3d[3*n+2];
    float px = rm[0]*X + rm[1]*Y + rm[2]*Z + rm[3];
    float py = rm[4]*X + rm[5]*Y + rm[6]*Z + rm[7];
    float pz = rm[8]*X + rm[9]*Y + rm[10]*Z + rm[11];
    float pw = rm[12]*X + rm[13]*Y + rm[14]*Z + rm[15];
    d_pts3d0[3*n]   = px / pw;
    d_pts3d0[3*n+1] = py / pw;
    d_pts3d0[3*n+2] = pz / pw;
}

// ---------------- init: relative = q @ inv(r) ----------------
__global__ void k_init_state(const float* __restrict__ q, const float* __restrict__ r) {
    double M[4][8];
    for (int i = 0; i < 4; i++)
        for (int j = 0; j < 4; j++) { M[i][j] = r[i*4+j]; M[i][4+j] = (i == j) ? 1.0 : 0.0; }
    for (int col = 0; col < 4; col++) {
        int piv = col; double best = fabs(M[col][col]);
        for (int i = col+1; i < 4; i++) if (fabs(M[i][col]) > best) { best = fabs(M[i][col]); piv = i; }
        if (piv != col) for (int j = 0; j < 8; j++) { double tmp = M[col][j]; M[col][j] = M[piv][j]; M[piv][j] = tmp; }
        double inv = 1.0 / M[col][col];
        for (int j = 0; j < 8; j++) M[col][j] *= inv;
        for (int i = 0; i < 4; i++) if (i != col) {
            double f = M[i][col];
            for (int j = 0; j < 8; j++) M[i][j] -= f * M[col][j];
        }
    }
    for (int i = 0; i < 3; i++) {
        for (int j = 0; j < 4; j++) {
            double s = 0.0;
            for (int k = 0; k < 4; k++) s += (double)q[i*4+k] * M[k][4+j];
            if (j < 3) { d_R[i*3+j] = (float)s; d_Rc[i*3+j] = (float)s; }
            else       { d_t[i] = (float)s; d_tc[i] = (float)s; }
        }
    }
    d_lam = 0.01f;
    d_sel = 0;
}

// ---------------- projection helper ----------------
__device__ __forceinline__ void project_pt(int n, const float* R, const float* t,
                                           const float* __restrict__ Km,
                                           float& px, float& py, float& pz,
                                           float& p2x, float& p2y) {
    float X = d_pts3d0[3*n], Y = d_pts3d0[3*n+1], Z = d_pts3d0[3*n+2];
    px = R[0]*X + R[1]*Y + R[2]*Z + t[0];
    py = R[3]*X + R[4]*Y + R[5]*Z + t[1];
    pz = R[6]*X + R[7]*Y + R[8]*Z + t[2];
    float qx = Km[0]*px + Km[1]*py + Km[2]*pz;
    float qy = Km[3]*px + Km[4]*py + Km[5]*pz;
    float qz = Km[6]*px + Km[7]*py + Km[8]*pz;
    p2x = qx / qz; p2y = qy / qz;
}

// ---------------- FUSED: candidate cost + channel sums at candidate pose ----------------
__global__ void __launch_bounds__(256) k_cost_jac(const float* __restrict__ Km) {
    int n = blockIdx.x;
    int tid = threadIdx.x;
    int wbuf = d_sel ^ 1;
    float R[9], t[3];
#pragma unroll
    for (int i = 0; i < 9; i++) R[i] = d_Rc[i];
#pragma unroll
    for (int i = 0; i < 3; i++) t[i] = d_tc[i];
    float px, py, pz, p2x, p2y;
    project_pt(n, R, t, Km, px, py, pz, p2x, p2y);
    float ix = fminf(fmaxf(p2x * SRINV, 0.f), (float)(WW-1));
    float iy = fminf(fmaxf(p2y * SRINV, 0.f), (float)(HH-1));
    BilinSetup s = bilin_setup(ix, iy);
    // gradient bilinear weights carry the fp8 un-scale factor
    float gw00 = s.w00 * GSCALE_INV, gw10 = s.w10 * GSCALE_INV;
    float gw01 = s.w01 * GSCALE_INV, gw11 = s.w11 * GSCALE_INV;

    const uint2* I1 = reinterpret_cast<const uint2*>(d_img1B);
    const uint2* G  = d_g8;
    const uint2* F0 = reinterpret_cast<const uint2*>(d_feat0B) + (size_t)n * C4;
    int c = tid;

    uint2 bi00 = I1[(size_t)s.b00*C4 + c], bi10 = I1[(size_t)s.b10*C4 + c];
    uint2 bi01 = I1[(size_t)s.b01*C4 + c], bi11 = I1[(size_t)s.b11*C4 + c];
    uint2 q00 = G[(size_t)s.b00*C4 + c];
    uint2 q10 = G[(size_t)s.b10*C4 + c];
    uint2 q01 = G[(size_t)s.b01*C4 + c];
    uint2 q11 = G[(size_t)s.b11*C4 + c];
    uint2 bf0 = F0[c];

    float i0v[4], i1v[4], i2v[4], i3v[4], f0v[4];
    unpack_b4(bi00, i0v); unpack_b4(bi10, i1v);
    unpack_b4(bi01, i2v); unpack_b4(bi11, i3v);
    unpack_b4(bf0, f0v);
    float gx00[4], gy00[4], gx10[4], gy10[4], gx01[4], gy01[4], gx11[4], gy11[4];
    unpack_f8x4(q00.x, gx00); unpack_f8x4(q00.y, gy00);
    unpack_f8x4(q10.x, gx10); unpack_f8x4(q10.y, gy10);
    unpack_f8x4(q01.x, gx01); unpack_f8x4(q01.y, gy01);
    unpack_f8x4(q11.x, gx11); unpack_f8x4(q11.y, gy11);

    float cst = 0.f, sx = 0.f, sy = 0.f, sxx = 0.f, sxy = 0.f, syy = 0.f;
#pragma unroll
    for (int j = 0; j < 4; j++) {
        float f1 = bil(i0v[j], i1v[j], i2v[j], i3v[j], s);
        float e  = f1 - f0v[j];
        float jx = gx00[j]*gw00 + gx10[j]*gw10 + gx01[j]*gw01 + gx11[j]*gw11;
        float jy = gy00[j]*gw00 + gy10[j]*gw10 + gy01[j]*gw01 + gy11[j]*gw11;
        cst += e*e;
        sx += jx*e; sy += jy*e;
        sxx += jx*jx; sxy += jx*jy; syy += jy*jy;
    }

#pragma unroll
    for (int off = 16; off; off >>= 1) {
        cst += __shfl_down_sync(0xffffffffu, cst, off);
        sx  += __shfl_down_sync(0xffffffffu, sx,  off);
        sy  += __shfl_down_sync(0xffffffffu, sy,  off);
        sxx += __shfl_down_sync(0xffffffffu, sxx, off);
        sxy += __shfl_down_sync(0xffffffffu, sxy, off);
        syy += __shfl_down_sync(0xffffffffu, syy, off);
    }
    __shared__ float sm[8][6];
    int wid = tid >> 5, lane = tid & 31;
    if (lane == 0) {
        sm[wid][0] = cst; sm[wid][1] = sx; sm[wid][2] = sy;
        sm[wid][3] = sxx; sm[wid][4] = sxy; sm[wid][5] = syy;
    }
    __syncthreads();
    if (tid == 0) {
        float CS = 0.f, SX = 0.f, SY = 0.f, SXX = 0.f, SXY = 0.f, SYY = 0.f;
#pragma unroll
        for (int w = 0; w < 8; w++) {
            CS += sm[w][0]; SX += sm[w][1]; SY += sm[w][2];
            SXX += sm[w][3]; SXY += sm[w][4]; SYY += sm[w][5];
        }
        d_costpt[n] = CS;
        d_candp2[2*n]   = p2x;
        d_candp2[2*n+1] = p2y;
        float* P = d_part[wbuf];
        P[0*NP + n] = SX;  P[1*NP + n] = SY;
        P[2*NP + n] = SXX; P[3*NP + n] = SXY; P[4*NP + n] = SYY;
        P[5*NP + n] = px;  P[6*NP + n] = py;  P[7*NP + n] = pz;
    }
}

// ---------------- FUSED: accept/reject + copy + build g/H + LM solve ----------------
__global__ void __launch_bounds__(256) k_update(int mode, const float* __restrict__ Km,
                                                float* __restrict__ out) {
    int tid = threadIdx.x;
    __shared__ float smc[256];
    __shared__ int s_acc, s_sel, s_redo;

    // ---- accept: reduce cost ----
    float acc = 0.f;
    for (int n = tid; n < NP; n += 256) acc += d_costpt[n];
    smc[tid] = acc;
    __syncthreads();
    for (int sgap = 128; sgap; sgap >>= 1) {
        if (tid < sgap) smc[tid] += smc[tid + sgap];
        __syncthreads();
    }
    if (tid == 0) {
        float newc = smc[0] / (float)NP;
        if (mode == 0) {
            d_prev = newc;
            d_sel = 1;
            s_sel = 1; s_redo = 1; s_acc = 1;
        } else {
            bool a = (newc <= d_prev);
            if (a) {
#pragma unroll
                for (int i = 0; i < 9; i++) d_R[i] = d_Rc[i];
#pragma unroll
                for (int i = 0; i < 3; i++) d_t[i] = d_tc[i];
                d_prev = newc;
                d_sel ^= 1;
            }
            float l = d_lam * (a ? 0.1f : 10.f);
            d_lam = fminf(fmaxf(l, 1e-6f), 100.f);
            s_acc = a ? 1 : 0;
            s_sel = d_sel;
            s_redo = a ? 1 : 0;
        }
    }
    __syncthreads();
    if (s_acc) {
        const float2* src = reinterpret_cast<const float2*>(d_candp2);
        float2* dst = reinterpret_cast<float2*>(out);
        for (int n = tid; n < NP; n += 256) dst[n] = src[n];
    }

    // ---- build + reduce g/H from per-point sums (only if accepted pose changed) ----
    if (s_redo) {
        const float* P = d_part[s_sel];
        float fx = Km[0], fy = Km[4];
        float a27[27];
#pragma unroll
        for (int k = 0; k < 27; k++) a27[k] = 0.f;
        for (int n = tid; n < NP; n += 256) {
            float SX  = P[0*NP + n], SY  = P[1*NP + n];
            float SXX = P[2*NP + n], SXY = P[3*NP + n], SYY = P[4*NP + n];
            float px = P[5*NP + n], py = P[6*NP + n], pz = P[7*NP + n];
            float invz = 1.f / pz;
            float sc = invz * SRINV;
            float a00 = fx * sc, a02 = -fx * px * invz * sc;
            float a11 = fy * sc, a12 = -fy * py * invz * sc;
            float A0[6], A1[6];
            A0[0] = a00; A0[1] = 0.f; A0[2] = a02;
            A1[0] = 0.f; A1[1] = a11; A1[2] = a12;
            A0[3] = a02*py;
            A0[4] = a00*pz - a02*px;
            A0[5] = -a00*py;
            A1[3] = -(a11*pz - a12*py);
            A1[4] = a12*px;
            A1[5] = a11*px;
#pragma unroll
            for (int k = 0; k < 6; k++)
                a27[k] += SX*A0[k] + SY*A1[k];
            int idx = 6;
#pragma unroll
            for (int k = 0; k < 6; k++)
#pragma unroll
                for (int l = k; l < 6; l++) {
                    a27[idx] += SXX*A0[k]*A0[l] + SXY*(A0[k]*A1[l] + A1[k]*A0[l]) + SYY*A1[k]*A1[l];
                    idx++;
                }
        }
        __shared__ float sm27[27][256];
#pragma unroll
        for (int k = 0; k < 27; k++) sm27[k][tid] = a27[k];
        __syncthreads();
        for (int sgap = 128; sgap; sgap >>= 1) {
            if (tid < sgap)
#pragma unroll
                for (int k = 0; k < 27; k++) sm27[k][tid] += sm27[k][tid + sgap];
            __syncthreads();
        }
        if (tid == 0) {
#pragma unroll
            for (int k = 0; k < 6; k++) d_gv[k] = sm27[k][0];
            int idx = 6;
            for (int k = 0; k < 6; k++)
                for (int l = k; l < 6; l++) {
                    d_Hm[k*6+l] = sm27[idx][0];
                    d_Hm[l*6+k] = sm27[idx][0];
                    idx++;
                }
        }
        __syncthreads();
    }
    if (tid != 0) return;

    // ---- fp32 LM solve, single thread ----
    float Hd[6][7];
    float lam = d_lam;
    for (int k = 0; k < 6; k++) {
        for (int l = 0; l < 6; l++) Hd[k][l] = d_Hm[k*6+l];
        Hd[k][k] += (d_Hm[k*6+k] + 1e-9f) * lam;
        Hd[k][6] = -d_gv[k];
    }
    for (int col = 0; col < 6; col++) {
        int piv = col; float best = fabsf(Hd[col][col]);
        for (int r = col+1; r < 6; r++) if (fabsf(Hd[r][col]) > best) { best = fabsf(Hd[r][col]); piv = r; }
        if (piv != col) for (int j = 0; j < 7; j++) { float tmp = Hd[col][j]; Hd[col][j] = Hd[piv][j]; Hd[piv][j] = tmp; }
        float ip = 1.0f / Hd[col][col];
        for (int r = col+1; r < 6; r++) {
            float f = Hd[r][col] * ip;
            for (int j = col; j < 7; j++) Hd[r][j] -= f * Hd[col][j];
        }
    }
    float delta[6];
    for (int r = 5; r >= 0; r--) {
        float sv = Hd[r][6];
        for (int j = r+1; j < 6; j++) sv -= Hd[r][j] * delta[j];
        delta[r] = sv / Hd[r][r];
    }
    float w0 = delta[3], w1 = delta[4], w2 = delta[5];
    float th2 = w0*w0 + w1*w1 + w2*w2;
    float th = sqrtf(fmaxf(th2, 1e-24f));
    float Ac = (th2 < 1e-16f) ? 1.0f : sinf(th) / th;
    float Bc = (th2 < 1e-16f) ? 0.5f : (1.0f - cosf(th)) / fmaxf(th2, 1e-24f);
    float dr[3][3];
    dr[0][0] = 1.0f + Bc*(w0*w0 - th2);
    dr[0][1] = -Ac*w2 + Bc*w0*w1;
    dr[0][2] =  Ac*w1 + Bc*w0*w2;
    dr[1][0] =  Ac*w2 + Bc*w1*w0;
    dr[1][1] = 1.0f + Bc*(w1*w1 - th2);
    dr[1][2] = -Ac*w0 + Bc*w1*w2;
    dr[2][0] = -Ac*w1 + Bc*w2*w0;
    dr[2][1] =  Ac*w0 + Bc*w2*w1;
    dr[2][2] = 1.0f + Bc*(w2*w2 - th2);
    for (int i = 0; i < 3; i++) {
        for (int j = 0; j < 3; j++) {
            float sv = 0.0f;
            for (int k = 0; k < 3; k++) sv += dr[i][k] * d_R[k*3+j];
            d_Rc[i*3+j] = sv;
        }
        float sv = delta[i];
        for (int k = 0; k < 3; k++) sv += dr[i][k] * d_t[k];
        d_tc[i] = sv;
    }
}

// ---------------- launch ----------------
extern "C" void kernel_launch(void* const* d_in, const int* in_sizes, int n_in,
                              void* d_out, int out_size) {
    const float* imgf0 = (const float*)d_in[0];
    const float* imgf1 = (const float*)d_in[1];
    const float* pts2d = (const float*)d_in[2];
    const float* pts3d = (const float*)d_in[3];
    const float* qm    = (const float*)d_in[4];
    const float* rm    = (const float*)d_in[5];
    const float* Km    = (const float*)d_in[6];
    float* out = (float*)d_out;

    dim3 tb(32, 8);
    k_transpose<<<dim3(HW/32, CC/32), tb>>>(imgf0, 0);
    k_transpose<<<dim3(HW/32, CC/32), tb>>>(imgf1, 1);
    k_sobel<<<dim3(WW, HH), 256>>>();
    k_feat0<<<NP, 256>>>(pts2d);
    k_pts3d0<<<NP/256, 256>>>(pts3d, rm);
    k_init_state<<<1, 1>>>(qm, rm);

    k_cost_jac<<<NP, 256>>>(Km);
    k_update<<<1, 256>>>(0, Km, out);

    for (int it = 0; it < NITERS; it++) {
        k_cost_jac<<<NP, 256>>>(Km);
        k_update<<<1, 256>>>(1, Km, out);
    }
}

// round 7
// speedup vs baseline: 2.1779x; 1.0963x over previous
#include <cuda_runtime.h>
#include <cuda_bf16.h>
#include <cuda_fp8.h>
#include <math.h>

#define CC 1024
#define C4 (CC/4)
#define HH 128
#define WW 128
#define HW (HH*WW)
#define NP 4096
#define SRINV 0.125f
#define NITERS 10
#define GSCALE 16.0f
#define GSCALE_INV (1.0f/16.0f)

// ---------------- device state ----------------
__device__ __nv_bfloat16 d_img0B[HW*CC];     // imgf0 [H,W,C] bf16
__device__ __nv_bfloat16 d_img1B[HW*CC];     // imgf1 [H,W,C] bf16 (staging for sobel)
__device__ uint4 d_ig[HW*C4];                // {img1 bf16x4 (x,y), gx fp8x4 (z), gy fp8x4 (w)}, grads pre-scaled by 16
__device__ __nv_bfloat16 d_feat0B[NP*CC];    // reference features bf16
__device__ float d_pts3d0[NP*3];
__device__ float d_part[2][8*NP];            // per-point: SX,SY,SXX,SXY,SYY,px,py,pz
__device__ float d_costpt[NP];
__device__ float d_candp2[NP*2];
__device__ float d_R[9];
__device__ float d_t[3];
__device__ float d_Rc[9];
__device__ float d_tc[3];
__device__ float d_lam;
__device__ float d_prev;
__device__ int   d_sel;
__device__ float d_Hm[36];
__device__ float d_gv[6];

// ---------------- prep: CHW fp32 -> HWC bf16 transpose ----------------
__global__ void k_transpose(const float* __restrict__ src, int dst_sel) {
    __nv_bfloat16* dst = dst_sel ? d_img1B : d_img0B;
    __shared__ float tile[32][33];
    int hw0 = blockIdx.x * 32;
    int c0  = blockIdx.y * 32;
#pragma unroll
    for (int i = threadIdx.y; i < 32; i += 8)
        tile[i][threadIdx.x] = src[(size_t)(c0 + i) * HW + hw0 + threadIdx.x];
    __syncthreads();
#pragma unroll
    for (int i = threadIdx.y; i < 32; i += 8)
        dst[(size_t)(hw0 + i) * CC + c0 + threadIdx.x] = __float2bfloat16(tile[threadIdx.x][i]);
}

// helpers
__device__ __forceinline__ void unpack_b4(uint2 q, float f[4]) {
    float2 a = __bfloat1622float2(*reinterpret_cast<__nv_bfloat162*>(&q.x));
    float2 b = __bfloat1622float2(*reinterpret_cast<__nv_bfloat162*>(&q.y));
    f[0] = a.x; f[1] = a.y; f[2] = b.x; f[3] = b.y;
}
__device__ __forceinline__ uint2 pack_b4(const float f[4]) {
    __nv_bfloat162 a = __floats2bfloat162_rn(f[0], f[1]);
    __nv_bfloat162 b = __floats2bfloat162_rn(f[2], f[3]);
    uint2 q;
    q.x = *reinterpret_cast<unsigned*>(&a);
    q.y = *reinterpret_cast<unsigned*>(&b);
    return q;
}
__device__ __forceinline__ unsigned pack_f8x4(const float f[4]) {
    __nv_fp8x2_storage_t lo = __nv_cvt_float2_to_fp8x2(make_float2(f[0], f[1]), __NV_SATFINITE, __NV_E4M3);
    __nv_fp8x2_storage_t hi = __nv_cvt_float2_to_fp8x2(make_float2(f[2], f[3]), __NV_SATFINITE, __NV_E4M3);
    return (unsigned)lo | ((unsigned)hi << 16);
}
__device__ __forceinline__ void unpack_f8x4(unsigned q, float f[4]) {
    __half2_raw h01 = __nv_cvt_fp8x2_to_halfraw2((__nv_fp8x2_storage_t)(q & 0xFFFF), __NV_E4M3);
    __half2_raw h23 = __nv_cvt_fp8x2_to_halfraw2((__nv_fp8x2_storage_t)(q >> 16),    __NV_E4M3);
    float2 a = __half22float2(*reinterpret_cast<__half2*>(&h01));
    float2 b = __half22float2(*reinterpret_cast<__half2*>(&h23));
    f[0] = a.x; f[1] = a.y; f[2] = b.x; f[3] = b.y;
}

// ---------------- prep: sobel -> combined {img1, gx, gy} stream ----------------
__global__ void __launch_bounds__(256) k_sobel() {
    int x = blockIdx.x, y = blockIdx.y;
    int c = threadIdx.x;
    const uint2* img = reinterpret_cast<const uint2*>(d_img1B);
    uint2 center = img[(size_t)(y * WW + x) * C4 + c];
    float v[3][3][4];
#pragma unroll
    for (int dy = -1; dy <= 1; dy++) {
#pragma unroll
        for (int dx = -1; dx <= 1; dx++) {
            int yy = y + dy, xx = x + dx;
            float f[4] = {0.f, 0.f, 0.f, 0.f};
            if (yy >= 0 && yy < HH && xx >= 0 && xx < WW) {
                uint2 q = img[(size_t)(yy * WW + xx) * C4 + c];
                unpack_b4(q, f);
            }
#pragma unroll
            for (int j = 0; j < 4; j++) v[dy+1][dx+1][j] = f[j];
        }
    }
    float gx[4], gy[4];
#pragma unroll
    for (int j = 0; j < 4; j++) {
        gx[j] = (v[0][2][j] - v[0][0][j] + 2.f*(v[1][2][j] - v[1][0][j]) + v[2][2][j] - v[2][0][j]) * (0.125f * GSCALE);
        gy[j] = (v[2][0][j] - v[0][0][j] + 2.f*(v[2][1][j] - v[0][1][j]) + v[2][2][j] - v[0][2][j]) * (0.125f * GSCALE);
    }
    uint4 o;
    o.x = center.x;
    o.y = center.y;
    o.z = pack_f8x4(gx);
    o.w = pack_f8x4(gy);
    d_ig[(size_t)(y * WW + x) * C4 + c] = o;
}

// ---------------- bilinear setup ----------------
struct BilinSetup {
    int b00, b10, b01, b11;
    float w00, w10, w01, w11;
};
__device__ __forceinline__ BilinSetup bilin_setup(float x, float y) {
    BilinSetup s;
    float x0f = floorf(x), y0f = floorf(y);
    float wx = x - x0f, wy = y - y0f;
    int x0 = min(max((int)x0f, 0), WW-1);
    int x1 = min(max(x0 + 1, 0), WW-1);
    int y0 = min(max((int)y0f, 0), HH-1);
    int y1 = min(max(y0 + 1, 0), HH-1);
    s.w00 = (1.f-wx)*(1.f-wy); s.w10 = wx*(1.f-wy);
    s.w01 = (1.f-wx)*wy;       s.w11 = wx*wy;
    s.b00 = (y0*WW + x0); s.b10 = (y0*WW + x1);
    s.b01 = (y1*WW + x0); s.b11 = (y1*WW + x1);
    return s;
}
__device__ __forceinline__ float bil(float a, float b, float c, float d, const BilinSetup& s) {
    return a*s.w00 + b*s.w10 + c*s.w01 + d*s.w11;
}

// ---------------- prep: feat0 (warp per point) ----------------
__global__ void __launch_bounds__(256) k_feat0(const float* __restrict__ pts2d) {
    int warp = threadIdx.x >> 5;
    int lane = threadIdx.x & 31;
    int n = blockIdx.x * 8 + warp;
    BilinSetup s = bilin_setup(pts2d[2*n] * SRINV, pts2d[2*n+1] * SRINV);
    const uint2* img = reinterpret_cast<const uint2*>(d_img0B);
    uint2* dst = reinterpret_cast<uint2*>(d_feat0B) + (size_t)n * C4;
#pragma unroll 4
    for (int j = 0; j < 8; j++) {
        int c = lane + 32*j;
        float f00[4], f10[4], f01[4], f11[4], o[4];
        unpack_b4(img[(size_t)s.b00*C4 + c], f00);
        unpack_b4(img[(size_t)s.b10*C4 + c], f10);
        unpack_b4(img[(size_t)s.b01*C4 + c], f01);
        unpack_b4(img[(size_t)s.b11*C4 + c], f11);
#pragma unroll
        for (int k = 0; k < 4; k++)
            o[k] = bil(f00[k], f10[k], f01[k], f11[k], s);
        dst[c] = pack_b4(o);
    }
}

// ---------------- prep: pts3d0 ----------------
__global__ void k_pts3d0(const float* __restrict__ p3d, const float* __restrict__ rm) {
    int n = blockIdx.x * blockDim.x + threadIdx.x;
    if (n >= NP) return;
    float X = p3d[3*n], Y = p3d[3*n+1], Z = p3d[3*n+2];
    float px = rm[0]*X + rm[1]*Y + rm[2]*Z + rm[3];
    float py = rm[4]*X + rm[5]*Y + rm[6]*Z + rm[7];
    float pz = rm[8]*X + rm[9]*Y + rm[10]*Z + rm[11];
    float pw = rm[12]*X + rm[13]*Y + rm[14]*Z + rm[15];
    d_pts3d0[3*n]   = px / pw;
    d_pts3d0[3*n+1] = py / pw;
    d_pts3d0[3*n+2] = pz / pw;
}

// ---------------- init: relative = q @ inv(r) ----------------
__global__ void k_init_state(const float* __restrict__ q, const float* __restrict__ r) {
    double M[4][8];
    for (int i = 0; i < 4; i++)
        for (int j = 0; j < 4; j++) { M[i][j] = r[i*4+j]; M[i][4+j] = (i == j) ? 1.0 : 0.0; }
    for (int col = 0; col < 4; col++) {
        int piv = col; double best = fabs(M[col][col]);
        for (int i = col+1; i < 4; i++) if (fabs(M[i][col]) > best) { best = fabs(M[i][col]); piv = i; }
        if (piv != col) for (int j = 0; j < 8; j++) { double tmp = M[col][j]; M[col][j] = M[piv][j]; M[piv][j] = tmp; }
        double inv = 1.0 / M[col][col];
        for (int j = 0; j < 8; j++) M[col][j] *= inv;
        for (int i = 0; i < 4; i++) if (i != col) {
            double f = M[i][col];
            for (int j = 0; j < 8; j++) M[i][j] -= f * M[col][j];
        }
    }
    for (int i = 0; i < 3; i++) {
        for (int j = 0; j < 4; j++) {
            double s = 0.0;
            for (int k = 0; k < 4; k++) s += (double)q[i*4+k] * M[k][4+j];
            if (j < 3) { d_R[i*3+j] = (float)s; d_Rc[i*3+j] = (float)s; }
            else       { d_t[i] = (float)s; d_tc[i] = (float)s; }
        }
    }
    d_lam = 0.01f;
    d_sel = 0;
}

// ---------------- projection helper ----------------
__device__ __forceinline__ void project_pt(int n, const float* R, const float* t,
                                           const float* __restrict__ Km,
                                           float& px, float& py, float& pz,
                                           float& p2x, float& p2y) {
    float X = d_pts3d0[3*n], Y = d_pts3d0[3*n+1], Z = d_pts3d0[3*n+2];
    px = R[0]*X + R[1]*Y + R[2]*Z + t[0];
    py = R[3]*X + R[4]*Y + R[5]*Z + t[1];
    pz = R[6]*X + R[7]*Y + R[8]*Z + t[2];
    float qx = Km[0]*px + Km[1]*py + Km[2]*pz;
    float qy = Km[3]*px + Km[4]*py + Km[5]*pz;
    float qz = Km[6]*px + Km[7]*py + Km[8]*pz;
    p2x = qx / qz; p2y = qy / qz;
}

// ---------------- FUSED: cost + channel sums, WARP PER POINT ----------------
__global__ void __launch_bounds__(256) k_cost_jac(const float* __restrict__ Km) {
    int warp = threadIdx.x >> 5;
    int lane = threadIdx.x & 31;
    int n = blockIdx.x * 8 + warp;
    int wbuf = d_sel ^ 1;
    float R[9], t[3];
#pragma unroll
    for (int i = 0; i < 9; i++) R[i] = d_Rc[i];
#pragma unroll
    for (int i = 0; i < 3; i++) t[i] = d_tc[i];
    float px, py, pz, p2x, p2y;
    project_pt(n, R, t, Km, px, py, pz, p2x, p2y);
    float ix = fminf(fmaxf(p2x * SRINV, 0.f), (float)(WW-1));
    float iy = fminf(fmaxf(p2y * SRINV, 0.f), (float)(HH-1));
    BilinSetup s = bilin_setup(ix, iy);
    float gw00 = s.w00 * GSCALE_INV, gw10 = s.w10 * GSCALE_INV;
    float gw01 = s.w01 * GSCALE_INV, gw11 = s.w11 * GSCALE_INV;

    const uint4* IG = d_ig;
    const uint2* F0 = reinterpret_cast<const uint2*>(d_feat0B) + (size_t)n * C4;

    float cst = 0.f, sx = 0.f, sy = 0.f, sxx = 0.f, sxy = 0.f, syy = 0.f;
#pragma unroll 4
    for (int j = 0; j < 8; j++) {
        int c = lane + 32*j;
        uint4 g00 = IG[(size_t)s.b00*C4 + c];
        uint4 g10 = IG[(size_t)s.b10*C4 + c];
        uint4 g01 = IG[(size_t)s.b01*C4 + c];
        uint4 g11 = IG[(size_t)s.b11*C4 + c];
        uint2 bf0 = F0[c];

        float i0v[4], i1v[4], i2v[4], i3v[4], f0v[4];
        unpack_b4(make_uint2(g00.x, g00.y), i0v);
        unpack_b4(make_uint2(g10.x, g10.y), i1v);
        unpack_b4(make_uint2(g01.x, g01.y), i2v);
        unpack_b4(make_uint2(g11.x, g11.y), i3v);
        unpack_b4(bf0, f0v);
        float gx00[4], gy00[4], gx10[4], gy10[4], gx01[4], gy01[4], gx11[4], gy11[4];
        unpack_f8x4(g00.z, gx00); unpack_f8x4(g00.w, gy00);
        unpack_f8x4(g10.z, gx10); unpack_f8x4(g10.w, gy10);
        unpack_f8x4(g01.z, gx01); unpack_f8x4(g01.w, gy01);
        unpack_f8x4(g11.z, gx11); unpack_f8x4(g11.w, gy11);

#pragma unroll
        for (int k = 0; k < 4; k++) {
            float f1 = bil(i0v[k], i1v[k], i2v[k], i3v[k], s);
            float e  = f1 - f0v[k];
            float jx = gx00[k]*gw00 + gx10[k]*gw10 + gx01[k]*gw01 + gx11[k]*gw11;
            float jy = gy00[k]*gw00 + gy10[k]*gw10 + gy01[k]*gw01 + gy11[k]*gw11;
            cst += e*e;
            sx += jx*e; sy += jy*e;
            sxx += jx*jx; sxy += jx*jy; syy += jy*jy;
        }
    }

#pragma unroll
    for (int off = 16; off; off >>= 1) {
        cst += __shfl_down_sync(0xffffffffu, cst, off);
        sx  += __shfl_down_sync(0xffffffffu, sx,  off);
        sy  += __shfl_down_sync(0xffffffffu, sy,  off);
        sxx += __shfl_down_sync(0xffffffffu, sxx, off);
        sxy += __shfl_down_sync(0xffffffffu, sxy, off);
        syy += __shfl_down_sync(0xffffffffu, syy, off);
    }
    if (lane == 0) {
        d_costpt[n] = cst;
        d_candp2[2*n]   = p2x;
        d_candp2[2*n+1] = p2y;
        float* P = d_part[wbuf];
        P[0*NP + n] = sx;  P[1*NP + n] = sy;
        P[2*NP + n] = sxx; P[3*NP + n] = sxy; P[4*NP + n] = syy;
        P[5*NP + n] = px;  P[6*NP + n] = py;  P[7*NP + n] = pz;
    }
}

// ---------------- FUSED: accept/reject + copy + build g/H + LM solve ----------------
__global__ void __launch_bounds__(256) k_update(int mode, const float* __restrict__ Km,
                                                float* __restrict__ out) {
    int tid = threadIdx.x;
    __shared__ float smc[256];
    __shared__ int s_acc, s_sel, s_redo;

    float acc = 0.f;
    for (int n = tid; n < NP; n += 256) acc += d_costpt[n];
    smc[tid] = acc;
    __syncthreads();
    for (int sgap = 128; sgap; sgap >>= 1) {
        if (tid < sgap) smc[tid] += smc[tid + sgap];
        __syncthreads();
    }
    if (tid == 0) {
        float newc = smc[0] / (float)NP;
        if (mode == 0) {
            d_prev = newc;
            d_sel = 1;
            s_sel = 1; s_redo = 1; s_acc = 1;
        } else {
            bool a = (newc <= d_prev);
            if (a) {
#pragma unroll
                for (int i = 0; i < 9; i++) d_R[i] = d_Rc[i];
#pragma unroll
                for (int i = 0; i < 3; i++) d_t[i] = d_tc[i];
                d_prev = newc;
                d_sel ^= 1;
            }
            float l = d_lam * (a ? 0.1f : 10.f);
            d_lam = fminf(fmaxf(l, 1e-6f), 100.f);
            s_acc = a ? 1 : 0;
            s_sel = d_sel;
            s_redo = a ? 1 : 0;
        }
    }
    __syncthreads();
    if (s_acc) {
        const float2* src = reinterpret_cast<const float2*>(d_candp2);
        float2* dst = reinterpret_cast<float2*>(out);
        for (int n = tid; n < NP; n += 256) dst[n] = src[n];
    }

    if (s_redo) {
        const float* P = d_part[s_sel];
        float fx = Km[0], fy = Km[4];
        float a27[27];
#pragma unroll
        for (int k = 0; k < 27; k++) a27[k] = 0.f;
        for (int n = tid; n < NP; n += 256) {
            float SX  = P[0*NP + n], SY  = P[1*NP + n];
            float SXX = P[2*NP + n], SXY = P[3*NP + n], SYY = P[4*NP + n];
            float px = P[5*NP + n], py = P[6*NP + n], pz = P[7*NP + n];
            float invz = 1.f / pz;
            float sc = invz * SRINV;
            float a00 = fx * sc, a02 = -fx * px * invz * sc;
            float a11 = fy * sc, a12 = -fy * py * invz * sc;
            float A0[6], A1[6];
            A0[0] = a00; A0[1] = 0.f; A0[2] = a02;
            A1[0] = 0.f; A1[1] = a11; A1[2] = a12;
            A0[3] = a02*py;
            A0[4] = a00*pz - a02*px;
            A0[5] = -a00*py;
            A1[3] = -(a11*pz - a12*py);
            A1[4] = a12*px;
            A1[5] = a11*px;
#pragma unroll
            for (int k = 0; k < 6; k++)
                a27[k] += SX*A0[k] + SY*A1[k];
            int idx = 6;
#pragma unroll
            for (int k = 0; k < 6; k++)
#pragma unroll
                for (int l = k; l < 6; l++) {
                    a27[idx] += SXX*A0[k]*A0[l] + SXY*(A0[k]*A1[l] + A1[k]*A0[l]) + SYY*A1[k]*A1[l];
                    idx++;
                }
        }
        __shared__ float sm27[27][256];
#pragma unroll
        for (int k = 0; k < 27; k++) sm27[k][tid] = a27[k];
        __syncthreads();
        for (int sgap = 128; sgap; sgap >>= 1) {
            if (tid < sgap)
#pragma unroll
                for (int k = 0; k < 27; k++) sm27[k][tid] += sm27[k][tid + sgap];
            __syncthreads();
        }
        if (tid == 0) {
#pragma unroll
            for (int k = 0; k < 6; k++) d_gv[k] = sm27[k][0];
            int idx = 6;
            for (int k = 0; k < 6; k++)
                for (int l = k; l < 6; l++) {
                    d_Hm[k*6+l] = sm27[idx][0];
                    d_Hm[l*6+k] = sm27[idx][0];
                    idx++;
                }
        }
        __syncthreads();
    }
    if (tid != 0) return;

    // ---- fp32 LM solve ----
    float Hd[6][7];
    float lam = d_lam;
    for (int k = 0; k < 6; k++) {
        for (int l = 0; l < 6; l++) Hd[k][l] = d_Hm[k*6+l];
        Hd[k][k] += (d_Hm[k*6+k] + 1e-9f) * lam;
        Hd[k][6] = -d_gv[k];
    }
    for (int col = 0; col < 6; col++) {
        int piv = col; float best = fabsf(Hd[col][col]);
        for (int r = col+1; r < 6; r++) if (fabsf(Hd[r][col]) > best) { best = fabsf(Hd[r][col]); piv = r; }
        if (piv != col) for (int j = 0; j < 7; j++) { float tmp = Hd[col][j]; Hd[col][j] = Hd[piv][j]; Hd[piv][j] = tmp; }
        float ip = 1.0f / Hd[col][col];
        for (int r = col+1; r < 6; r++) {
            float f = Hd[r][col] * ip;
            for (int j = col; j < 7; j++) Hd[r][j] -= f * Hd[col][j];
        }
    }
    float delta[6];
    for (int r = 5; r >= 0; r--) {
        float sv = Hd[r][6];
        for (int j = r+1; j < 6; j++) sv -= Hd[r][j] * delta[j];
        delta[r] = sv / Hd[r][r];
    }
    float w0 = delta[3], w1 = delta[4], w2 = delta[5];
    float th2 = w0*w0 + w1*w1 + w2*w2;
    float th = sqrtf(fmaxf(th2, 1e-24f));
    float Ac = (th2 < 1e-16f) ? 1.0f : sinf(th) / th;
    float Bc = (th2 < 1e-16f) ? 0.5f : (1.0f - cosf(th)) / fmaxf(th2, 1e-24f);
    float dr[3][3];
    dr[0][0] = 1.0f + Bc*(w0*w0 - th2);
    dr[0][1] = -Ac*w2 + Bc*w0*w1;
    dr[0][2] =  Ac*w1 + Bc*w0*w2;
    dr[1][0] =  Ac*w2 + Bc*w1*w0;
    dr[1][1] = 1.0f + Bc*(w1*w1 - th2);
    dr[1][2] = -Ac*w0 + Bc*w1*w2;
    dr[2][0] = -Ac*w1 + Bc*w2*w0;
    dr[2][1] =  Ac*w0 + Bc*w2*w1;
    dr[2][2] = 1.0f + Bc*(w2*w2 - th2);
    for (int i = 0; i < 3; i++) {
        for (int j = 0; j < 3; j++) {
            float sv = 0.0f;
            for (int k = 0; k < 3; k++) sv += dr[i][k] * d_R[k*3+j];
            d_Rc[i*3+j] = sv;
        }
        float sv = delta[i];
        for (int k = 0; k < 3; k++) sv += dr[i][k] * d_t[k];
        d_tc[i] = sv;
    }
}

// ---------------- launch ----------------
extern "C" void kernel_launch(void* const* d_in, const int* in_sizes, int n_in,
                              void* d_out, int out_size) {
    const float* imgf0 = (const float*)d_in[0];
    const float* imgf1 = (const float*)d_in[1];
    const float* pts2d = (const float*)d_in[2];
    const float* pts3d = (const float*)d_in[3];
    const float* qm    = (const float*)d_in[4];
    const float* rm    = (const float*)d_in[5];
    const float* Km    = (const float*)d_in[6];
    float* out = (float*)d_out;

    dim3 tb(32, 8);
    k_transpose<<<dim3(HW/32, CC/32), tb>>>(imgf0, 0);
    k_transpose<<<dim3(HW/32, CC/32), tb>>>(imgf1, 1);
    k_sobel<<<dim3(WW, HH), 256>>>();
    k_feat0<<<NP/8, 256>>>(pts2d);
    k_pts3d0<<<NP/256, 256>>>(pts3d, rm);
    k_init_state<<<1, 1>>>(qm, rm);

    k_cost_jac<<<NP/8, 256>>>(Km);
    k_update<<<1, 256>>>(0, Km, out);

    for (int it = 0; it < NITERS; it++) {
        k_cost_jac<<<NP/8, 256>>>(Km);
        k_update<<<1, 256>>>(1, Km, out);
    }
}